// round 13
// baseline (speedup 1.0000x reference)
#include <cuda_runtime.h>
#include <cuda_bf16.h>
#include <math.h>

#define EPSF 1e-5f
typedef __nv_bfloat16 bf16;

// ---------------- scratch -----------------------------------------------------
__device__ bf16  g_ph[33554432];
__device__ bf16  g_pl[33554432];
__device__ bf16  g_bh[67108864];
__device__ bf16  g_bl[67108864];
__device__ bf16  g_xh[16777216];
__device__ bf16  g_xl[16777216];
__device__ bf16  g_wh[524288];
__device__ bf16  g_wl[524288];
__device__ float g_psum[524288];
__device__ float g_psq[524288];
__device__ float g_tmp[8388608];
__device__ float g_xm[32*64*484];
__device__ float g_gsum[32*64*484];
__device__ float g_x4p[32*64*1024];
__device__ unsigned char g_idx1[32*64*1024];
__device__ float g_xp[32*64*256];
__device__ unsigned char g_idx2[32*64*256];
__device__ float g_hb[32*64*256];
__device__ float g_a1b[32*64*256];
__device__ float g_a2b[32*64*256];
__device__ float g_a1s[32*32*256];
__device__ float g_a2s[32*32*256];
__device__ float g_sigb[32*2*256];
__device__ float g_attnb[32*64*256];
__device__ float g_gaout[32*64*1024];
__device__ float g_mean[1024];
__device__ float g_istd[1024];

__device__ __forceinline__ float sigmoidf_(float v){ return 1.0f/(1.0f+expf(-v)); }
__device__ __forceinline__ void split_store(float v, bf16* h, bf16* l, size_t i){
  bf16 hh=__float2bfloat16(v);
  h[i]=hh; l[i]=__float2bfloat16(v-__bfloat162float(hh));
}
__device__ __forceinline__ void cpa16(void* s, const void* g){
  unsigned sa=(unsigned)__cvta_generic_to_shared(s);
  asm volatile("cp.async.ca.shared.global [%0],[%1],16;"::"r"(sa),"l"(g));
}
__device__ __forceinline__ void ldmx4(unsigned* r, const bf16* p){
  unsigned a=(unsigned)__cvta_generic_to_shared(p);
  asm volatile("ldmatrix.sync.aligned.m8n8.x4.shared.b16 {%0,%1,%2,%3},[%4];"
   :"=r"(r[0]),"=r"(r[1]),"=r"(r[2]),"=r"(r[3]):"r"(a));
}
__device__ __forceinline__ void ldmx4t(unsigned* r, const bf16* p){
  unsigned a=(unsigned)__cvta_generic_to_shared(p);
  asm volatile("ldmatrix.sync.aligned.m8n8.x4.trans.shared.b16 {%0,%1,%2,%3},[%4];"
   :"=r"(r[0]),"=r"(r[1]),"=r"(r[2]),"=r"(r[3]):"r"(a));
}
__device__ __forceinline__ void mma16816(float* c,const unsigned* a,const unsigned* b){
  asm volatile("mma.sync.aligned.m16n8k16.row.col.f32.bf16.bf16.f32 "
    "{%0,%1,%2,%3},{%4,%5,%6,%7},{%8,%9},{%0,%1,%2,%3};"
    :"+f"(c[0]),"+f"(c[1]),"+f"(c[2]),"+f"(c[3])
    :"r"(a[0]),"r"(a[1]),"r"(a[2]),"r"(a[3]),"r"(b[0]),"r"(b[1]));
}

// ---------------- B stagers (BK=32) --------------------------------------------
#define PBP 136
#define PA_P 40
struct BSCopy {
  const bf16 *bh, *bl;
  __device__ __forceinline__ void stage(bf16* Bh, bf16* Bl, int k0, int n0, int tid) const {
#pragma unroll
    for(int it=0;it<2;it++){
      int id=it*256+tid; int k=id>>4, nc=(id&15)*8;
      cpa16(&Bh[k*PBP+nc], bh+(size_t)(k0+k)*131072+n0+nc);
      cpa16(&Bl[k*PBP+nc], bl+(size_t)(k0+k)*131072+n0+nc);
    }
  }
};
struct BSIm2col {
  const bf16 *xh, *xl;
  __device__ __forceinline__ void stage(bf16* Bh, bf16* Bl, int k0, int n0, int tid) const {
#pragma unroll
    for(int it=0;it<16;it++){
      int id=it*256+tid; int k=id>>7, n=id&127;
      int kk=k0+k;
      int ic=kk/9; int t=kk-ic*9; int dy=t/3-1, dx=t%3-1;
      int na=n0+n; int p=na&4095;
      int h=(p>>6)+dy, w=(p&63)+dx;
      bf16 vh, vl;
      if((unsigned)h>63u||(unsigned)w>63u){ vh=__float2bfloat16(0.f); vl=vh; }
      else{
        size_t gi=(size_t)ic*131072+(size_t)(na&~4095)+h*64+w;
        vh=xh[gi]; vl=xl[gi];
      }
      Bh[k*PBP+n]=vh; Bl[k*PBP+n]=vl;
    }
  }
};

// ---------------- epilogues ---------------------------------------------------
struct EpStore {
  float* o; int MC; int oc0;
  __device__ __forceinline__ void operator()(int m,int n,float a) const {
    int b=n>>12,p=n&4095;
    o[((size_t)(b*MC+oc0+m)<<12)+p]=a;
  }
};
struct EpSplitStore {
  bf16 *oh,*ol;
  __device__ __forceinline__ void operator()(int m,int n,float a) const {
    split_store(a, oh, ol, (size_t)m*131072+n);
  }
};
struct EpGateMulSplit {
  bf16 *ph,*pl; const float* x;
  __device__ __forceinline__ void operator()(int m,int n,float a) const {
    int b=n>>12,p=n&4095;
    float v=x[((size_t)(b*256+m)<<12)+p]*sigmoidf_(a);
    split_store(v, ph, pl, (size_t)m*131072+n);
  }
};
struct EpResidual {
  float* o; const float* x;
  __device__ __forceinline__ void operator()(int m,int n,float a) const {
    int b=n>>12,p=n&4095;
    size_t i=((size_t)(b*256+m)<<12)+p;
    o[i]=x[i]+a;
  }
};

// ------- legacy tensor-core GEMM: BK=32, 3-pass MMA, single barrier/k-tile ------
// BNORMOWN: normalize own staged chunks (BSCopy mapping) before the barrier.
template<int BM,bool STATS,bool BNORMOWN,class BS,class EP>
__global__ __launch_bounds__(256,2)
void tg2_k(const bf16* __restrict__ wh, const bf16* __restrict__ wl,
           int K, BS bs, EP ep,
           float* __restrict__ psum, float* __restrict__ psq, int C,
           const float* __restrict__ mean, const float* __restrict__ istd){
  constexpr int WTM=BM/2, MI=WTM/16;
  extern __shared__ __align__(16) bf16 SM[];
  bf16* AH[2]={SM, SM+BM*PA_P};
  bf16* AL[2]={SM+2*BM*PA_P, SM+3*BM*PA_P};
  bf16* BH[2]={SM+4*BM*PA_P, SM+4*BM*PA_P+32*PBP};
  bf16* BL[2]={SM+4*BM*PA_P+2*32*PBP, SM+4*BM*PA_P+3*32*PBP};
  __shared__ float sS4[4*BM], sQ4[4*BM];
  const int tid=threadIdx.x;
  const int warp=tid>>5, lane=tid&31;
  const int wm=warp>>2, wn=warp&3;
  const int m0=blockIdx.x*BM, n0=blockIdx.y*128;
  float c[MI][4][4];
#pragma unroll
  for(int i=0;i<MI;i++)
#pragma unroll
    for(int j=0;j<4;j++)
#pragma unroll
      for(int q=0;q<4;q++) c[i][j][q]=0.f;
  auto stageA=[&](int buf,int k0){
    for(int id=tid; id<BM*4; id+=256){
      int m=id>>2, kc=(id&3)*8;
      cpa16(&AH[buf][m*PA_P+kc], wh+(size_t)(m0+m)*K+k0+kc);
      cpa16(&AL[buf][m*PA_P+kc], wl+(size_t)(m0+m)*K+k0+kc);
    }
  };
  const int KT=K/32;
  stageA(0,0);
  bs.stage(BH[0],BL[0],0,n0,tid);
  asm volatile("cp.async.commit_group;");
  int buf=0;
  for(int kt=0;kt<KT;kt++){
    if(kt+1<KT){
      stageA(buf^1,(kt+1)*32);
      bs.stage(BH[buf^1],BL[buf^1],(kt+1)*32,n0,tid);
      asm volatile("cp.async.commit_group;");
      asm volatile("cp.async.wait_group 1;");
    } else {
      asm volatile("cp.async.wait_group 0;");
    }
    if(BNORMOWN){
      // normalize exactly the chunks this thread staged (BSCopy mapping);
      // visible after wait_group, so no extra barrier needed.
#pragma unroll
      for(int it=0;it<2;it++){
        int id=it*256+tid; int k=id>>4, nc=(id&15)*8;
        float mm=__ldg(&mean[kt*32+k]), is=__ldg(&istd[kt*32+k]);
        bf16* bph=&BH[buf][k*PBP+nc];
        bf16* bpl=&BL[buf][k*PBP+nc];
#pragma unroll
        for(int e=0;e<8;e++){
          float v=__bfloat162float(bph[e])+__bfloat162float(bpl[e]);
          v=(v-mm)*is; v=v>0.f?v:0.f;
          bf16 hh=__float2bfloat16(v);
          bph[e]=hh; bpl[e]=__float2bfloat16(v-__bfloat162float(hh));
        }
      }
    }
    __syncthreads();
    // ---- two k16 sub-steps, 3 independent-MMA passes each ---------------------
    const int arow=lane&15, acol=(lane>>4)<<3;
#pragma unroll
    for(int kk=0;kk<32;kk+=16){
      unsigned a4[MI][4];
      unsigned b4h[2][4], b4l[2][4];
#pragma unroll
      for(int np=0;np<2;np++){
        int rb=(kk+(lane&15))*PBP+wn*32+np*16+((lane>>4)<<3);
        ldmx4t(b4h[np], &BH[buf][rb]);
        ldmx4t(b4l[np], &BL[buf][rb]);
      }
#pragma unroll
      for(int mi=0;mi<MI;mi++)
        ldmx4(a4[mi], &AH[buf][(wm*WTM+mi*16+arow)*PA_P+kk+acol]);
#pragma unroll
      for(int np=0;np<2;np++)
#pragma unroll
        for(int t2=0;t2<2;t2++)
#pragma unroll
          for(int mi=0;mi<MI;mi++)
            mma16816(c[mi][np*2+t2], a4[mi], &b4h[np][t2*2]);
#pragma unroll
      for(int np=0;np<2;np++)
#pragma unroll
        for(int t2=0;t2<2;t2++)
#pragma unroll
          for(int mi=0;mi<MI;mi++)
            mma16816(c[mi][np*2+t2], a4[mi], &b4l[np][t2*2]);
#pragma unroll
      for(int mi=0;mi<MI;mi++)
        ldmx4(a4[mi], &AL[buf][(wm*WTM+mi*16+arow)*PA_P+kk+acol]);
#pragma unroll
      for(int np=0;np<2;np++)
#pragma unroll
        for(int t2=0;t2<2;t2++)
#pragma unroll
          for(int mi=0;mi<MI;mi++)
            mma16816(c[mi][np*2+t2], a4[mi], &b4h[np][t2*2]);
    }
    __syncthreads();
    buf^=1;
  }
  if(STATS){
#pragma unroll
    for(int mi=0;mi<MI;mi++){
      float s1=0.f,q1=0.f,s2=0.f,q2=0.f;
#pragma unroll
      for(int ni=0;ni<4;ni++){
        s1+=c[mi][ni][0]+c[mi][ni][1];
        q1+=c[mi][ni][0]*c[mi][ni][0]+c[mi][ni][1]*c[mi][ni][1];
        s2+=c[mi][ni][2]+c[mi][ni][3];
        q2+=c[mi][ni][2]*c[mi][ni][2]+c[mi][ni][3]*c[mi][ni][3];
      }
#pragma unroll
      for(int off=1;off<4;off<<=1){
        s1+=__shfl_xor_sync(0xffffffffu,s1,off);
        q1+=__shfl_xor_sync(0xffffffffu,q1,off);
        s2+=__shfl_xor_sync(0xffffffffu,s2,off);
        q2+=__shfl_xor_sync(0xffffffffu,q2,off);
      }
      if((lane&3)==0){
        int mr=wm*WTM+mi*16+(lane>>2);
        sS4[wn*BM+mr]=s1; sQ4[wn*BM+mr]=q1;
        sS4[wn*BM+mr+8]=s2; sQ4[wn*BM+mr+8]=q2;
      }
    }
    __syncthreads();
    for(int i=tid;i<BM;i+=256){
      float s=sS4[i]+sS4[BM+i]+sS4[2*BM+i]+sS4[3*BM+i];
      float q=sQ4[i]+sQ4[BM+i]+sQ4[2*BM+i]+sQ4[3*BM+i];
      psum[(size_t)blockIdx.y*C+m0+i]=s;
      psq [(size_t)blockIdx.y*C+m0+i]=q;
    }
  }
  const int r=lane>>2, q=lane&3;
#pragma unroll
  for(int mi=0;mi<MI;mi++)
#pragma unroll
    for(int ni=0;ni<4;ni++){
      int m=m0+wm*WTM+mi*16+r;
      int n=n0+wn*32+ni*8+2*q;
      ep(m,   n,   c[mi][ni][0]);
      ep(m,   n+1, c[mi][ni][1]);
      ep(m+8, n,   c[mi][ni][2]);
      ep(m+8, n+1, c[mi][ni][3]);
    }
}
#define SMEM128 (4*128*PA_P*2 + 4*32*PBP*2)
#define SMEM64  (4*64*PA_P*2  + 4*32*PBP*2)

// ---------------- stats finalize -----------------------------------------------
__global__ void bn_fin_k(const float* __restrict__ psum, const float* __restrict__ psq,
                         int C, float* __restrict__ mean, float* __restrict__ istd){
  int c=blockIdx.x;
  float s=0.f,q=0.f;
  for(int i=threadIdx.x;i<1024;i+=256){ s+=psum[(size_t)i*C+c]; q+=psq[(size_t)i*C+c]; }
  __shared__ float sh[256], sh2[256];
  sh[threadIdx.x]=s; sh2[threadIdx.x]=q; __syncthreads();
  for(int o=128;o>0;o>>=1){
    if(threadIdx.x<o){ sh[threadIdx.x]+=sh[threadIdx.x+o]; sh2[threadIdx.x]+=sh2[threadIdx.x+o]; }
    __syncthreads();
  }
  if(threadIdx.x==0){
    float m=sh[0]*(1.f/131072.f);
    float v=sh2[0]*(1.f/131072.f)-m*m;
    mean[c]=m; istd[c]=rsqrtf(v+EPSF);
  }
}

// ---------------- split kernels ---------------------------------------------------
__global__ void wsplit_all_k(const float* __restrict__ w1,const float* __restrict__ w2,
                             const float* __restrict__ w3,const float* __restrict__ w4,
                             const float* __restrict__ w5,
                             bf16* __restrict__ h, bf16* __restrict__ l){
  int i=blockIdx.x*blockDim.x+threadIdx.x;
  if(i>=331776) return;
  const float* src; int off;
  if(i<16384){src=w1;off=0;}
  else if(i<32768){src=w2;off=16384;}
  else if(i<69632){src=w3;off=32768;}
  else if(i<200704){src=w4;off=69632;}
  else {src=w5;off=200704;}
  split_store(src[i-off], h, l, i);
}
__global__ void xsplit_k(const float* __restrict__ x, bf16* __restrict__ xh,
                         bf16* __restrict__ xl){
  int i=blockIdx.x*blockDim.x+threadIdx.x;
  if(i>=32*128*4096) return;
  int p=i&4095; int bc=i>>12; int ch=bc&127; int b=bc>>7;
  float v=x[((size_t)(b*256+ch)<<12)+p];
  split_store(v, xh, xl, (size_t)ch*131072+b*4096+p);
}
__global__ void bn_stats_k(const float* __restrict__ d, int C, int S,
                           float* __restrict__ mean, float* __restrict__ istd){
  int c=blockIdx.x;
  double s=0.0,s2=0.0;
  for(int b=0;b<32;b++){
    const float* P=d+(size_t)(b*C+c)*S;
    for(int off=threadIdx.x;off<S;off+=256){
      float v=P[off]; s+=(double)v; s2+=(double)v*(double)v;
    }
  }
  __shared__ double sh[256], sh2[256];
  sh[threadIdx.x]=s; sh2[threadIdx.x]=s2; __syncthreads();
  for(int o=128;o>0;o>>=1){
    if(threadIdx.x<o){ sh[threadIdx.x]+=sh[threadIdx.x+o]; sh2[threadIdx.x]+=sh2[threadIdx.x+o]; }
    __syncthreads();
  }
  if(threadIdx.x==0){
    double N=32.0*(double)S;
    double m=sh[0]/N, v=sh2[0]/N-m*m;
    mean[c]=(float)m; istd[c]=rsqrtf((float)v+EPSF);
  }
}
__global__ void la_apply_k(const float* __restrict__ t, bf16* __restrict__ ph,
                           bf16* __restrict__ pl,
                           const float* __restrict__ mean, const float* __restrict__ istd){
  int i=blockIdx.x*blockDim.x+threadIdx.x;
  if(i>=32*64*4096) return;
  int p=i&4095; int bc=i>>12; int c=bc&63; int b=bc>>6;
  float v=(t[i]-mean[c])*istd[c];
  v=v>0.f?v:0.f;
  split_store(v, ph, pl, (size_t)(64+c)*131072+b*4096+p);
}
__global__ void blurpool_k(const float* __restrict__ x, float* __restrict__ xm){
  int i=blockIdx.x*blockDim.x+threadIdx.x;
  if(i>=32*64*484) return;
  int s=i%484; int bc=i/484; int c=bc&63; int b=bc>>6;
  const float* X=x+(((size_t)(b*256+128+c))<<12);
  int oh=s/22, ow=s%22;
  const float f0[4]={1.f,3.f,3.f,1.f};
  float acc=0.f;
  for(int iy=0;iy<4;iy++){
    int u=3*oh+iy-1; u=u<0?-u:u; u=u>63?126-u:u;
    float fy=f0[iy];
    for(int ix=0;ix<4;ix++){
      int v=3*ow+ix-1; v=v<0?-v:v; v=v>63?126-v:v;
      float m=-3.4e38f;
      for(int dy=-1;dy<=1;dy++){
        int yy=u+dy; if((unsigned)yy>63u) continue;
        for(int dx=-1;dx<=1;dx++){
          int xx=v+dx; if((unsigned)xx>63u) continue;
          float vv=X[yy*64+xx]; m=vv>m?vv:m;
        }
      }
      acc+=fy*f0[ix]*m;
    }
  }
  xm[i]=acc*(1.f/64.f);
}
__global__ void mra_strips_k(const float* __restrict__ wh1, const float* __restrict__ wv1,
                             const float* __restrict__ wh2, const float* __restrict__ wv2,
                             const float* __restrict__ xm, float* __restrict__ gsum){
  int i=blockIdx.x*blockDim.x+threadIdx.x;
  if(i>=32*64*484) return;
  int s=i%484; int bc=i/484; int c=bc&63;
  int r=s/22, cc=s%22;
  const float* X=xm+(size_t)bc*484;
  const float* W1=wh1+c*33; const float* V1=wv1+c*33;
  const float* W2=wh2+c*33; const float* V2=wv2+c*33;
  float acc=0.f;
  for(int ky=0;ky<11;ky++){
    int y=r+ky-5; if((unsigned)y>=22u) continue;
    for(int kx=0;kx<3;kx++){
      int x2=cc+kx-1; if((unsigned)x2>=22u) continue;
      acc+=W1[ky*3+kx]*X[y*22+x2];
    }
  }
  for(int ky=0;ky<3;ky++){
    int y=r+ky-1; if((unsigned)y>=22u) continue;
    for(int kx=0;kx<11;kx++){
      int x2=cc+kx-5; if((unsigned)x2>=22u) continue;
      acc+=V1[ky*11+kx]*X[y*22+x2];
    }
  }
  {
    int i2=r*44+cc; int R=i2/43, C=i2-43*R;
    for(int ky=0;ky<11;ky++){
      int RR=R+ky-5; if((unsigned)RR>=22u) continue;
      for(int kx=0;kx<3;kx++){
        int CC=C+kx-1; if((unsigned)CC>=43u) continue;
        int j=RR*43+CC; int q=j/44, m=j-44*q;
        if(m<22) acc+=W2[ky*3+kx]*X[q*22+m];
      }
    }
  }
  {
    int j=cc*44+r; int b2=j/43, a2=j-43*b2;
    for(int ky=0;ky<3;ky++){
      int RR=a2+ky-1; if((unsigned)RR>=43u) continue;
      for(int kx=0;kx<11;kx++){
        int CC=b2+kx-5; if((unsigned)CC>=22u) continue;
        int j2=CC*43+RR; int q=j2/44, m=j2-44*q;
        if(m<22) acc+=V2[ky*11+kx]*X[m*22+q];
      }
    }
  }
  gsum[i]=acc;
}
__global__ void mra_apply_k(const float* __restrict__ x, const float* __restrict__ gsum,
                            bf16* __restrict__ ph, bf16* __restrict__ pl,
                            const float* __restrict__ mean, const float* __restrict__ istd){
  int i=blockIdx.x*blockDim.x+threadIdx.x;
  if(i>=32*64*4096) return;
  int p=i&4095, bc=i>>12, c=bc&63, b=bc>>6;
  int h=p>>6, w=p&63;
  int ri=(h*22)>>6, ci=(w*22)>>6;
  float g=gsum[(size_t)bc*484+ri*22+ci];
  g=sigmoidf_((g-mean[c])*istd[c]);
  float v=x[((size_t)(b*256+128+c)<<12)+p]*g;
  split_store(v, ph, pl, (size_t)(128+c)*131072+b*4096+p);
}
__global__ void pool2_k(const float* __restrict__ in, long bstride, int c0, int inW,
                        float* __restrict__ out, unsigned char* __restrict__ idx, int total){
  int i=blockIdx.x*blockDim.x+threadIdx.x;
  if(i>=total) return;
  int outW=inW>>1; int os=outW*outW;
  int s=i%os; int bc=i/os; int b=bc>>6, c=bc&63;
  int oh=s/outW, ow=s-oh*outW;
  const float* P=in+(size_t)b*bstride+(size_t)(c0+c)*inW*inW;
  float v0=P[(2*oh)*inW+2*ow],   v1=P[(2*oh)*inW+2*ow+1];
  float v2=P[(2*oh+1)*inW+2*ow], v3=P[(2*oh+1)*inW+2*ow+1];
  float best=v0; int bi=0;
  if(v1>best){best=v1;bi=1;}
  if(v2>best){best=v2;bi=2;}
  if(v3>best){best=v3;bi=3;}
  out[i]=best; idx[i]=(unsigned char)bi;
}
__global__ void ga_proj1_k(const float* __restrict__ xp, const float* __restrict__ w,
                           const float* __restrict__ bias, float* __restrict__ hb){
  int i=blockIdx.x*blockDim.x+threadIdx.x;
  if(i>=32*64*256) return;
  int s=i&255; int boc=i>>8; int oc=boc&63; int b=boc>>6;
  const float* X=xp+(size_t)b*64*256;
  float acc=bias[oc];
  for(int ic=0;ic<64;ic++) acc+=w[oc*64+ic]*X[ic*256+s];
  hb[i]=acc>0.f?acc:0.f;
}
__global__ void ga_dw_k(const float* __restrict__ hb,
                        const float* __restrict__ c0w, const float* __restrict__ c0b,
                        const float* __restrict__ spw, const float* __restrict__ spb,
                        float* __restrict__ a1, float* __restrict__ a2){
  int bc=blockIdx.x; int c=bc&63;
  int s=threadIdx.x;
  int y=s>>4, x=s&15;
  __shared__ float A1[256];
  const float* H=hb+(size_t)bc*256;
  float acc=c0b[c];
  for(int ky=0;ky<5;ky++){
    int yy=y+ky-2; if((unsigned)yy>15u) continue;
    for(int kx=0;kx<5;kx++){
      int xx=x+kx-2; if((unsigned)xx>15u) continue;
      acc+=c0w[c*25+ky*5+kx]*H[yy*16+xx];
    }
  }
  A1[s]=acc; a1[(size_t)bc*256+s]=acc;
  __syncthreads();
  float acc2=spb[c];
  for(int ky=0;ky<7;ky++){
    int yy=y+3*ky-9; if((unsigned)yy>15u) continue;
    for(int kx=0;kx<7;kx++){
      int xx=x+3*kx-9; if((unsigned)xx>15u) continue;
      acc2+=spw[c*49+ky*7+kx]*A1[yy*16+xx];
    }
  }
  a2[(size_t)bc*256+s]=acc2;
}
__global__ void ga_c1c2_k(const float* __restrict__ a1, const float* __restrict__ a2,
                          const float* __restrict__ c1w, const float* __restrict__ c1b,
                          const float* __restrict__ c2w, const float* __restrict__ c2b,
                          float* __restrict__ a1s, float* __restrict__ a2s){
  int i=blockIdx.x*blockDim.x+threadIdx.x;
  if(i>=2*32*32*256) return;
  int which=i/(32*32*256); int rr=i-which*(32*32*256);
  int s=rr&255; int bj=rr>>8; int j=bj&31; int b=bj>>5;
  const float* src=which?a2:a1;
  const float* W=which?c2w:c1w;
  const float* Bb=which?c2b:c1b;
  const float* S=src+(size_t)b*64*256;
  float acc=Bb[j];
  for(int ic=0;ic<64;ic++) acc+=W[j*64+ic]*S[ic*256+s];
  (which?a2s:a1s)[(size_t)(b*32+j)*256+s]=acc;
}
__global__ void ga_aggsq_k(const float* __restrict__ a1s, const float* __restrict__ a2s,
                           const float* __restrict__ sqw, const float* __restrict__ sqb,
                           float* __restrict__ sg){
  int b=blockIdx.x; int s=threadIdx.x;
  __shared__ float AG[2][256];
  const float* A1=a1s+(size_t)b*32*256;
  const float* A2=a2s+(size_t)b*32*256;
  float sum=0.f, mx=-3.4e38f;
  for(int j=0;j<32;j++){
    float v1=A1[j*256+s]; sum+=v1; mx=v1>mx?v1:mx;
    float v2=A2[j*256+s]; sum+=v2; mx=v2>mx?v2:mx;
  }
  AG[0][s]=sum*(1.f/64.f); AG[1][s]=mx;
  __syncthreads();
  int y=s>>4, x=s&15;
  for(int o=0;o<2;o++){
    float acc=sqb[o];
    for(int ic=0;ic<2;ic++){
      const float* W=sqw+((o*2+ic)*49);
      for(int ky=0;ky<7;ky++){
        int yy=y+ky-3; if((unsigned)yy>15u) continue;
        for(int kx=0;kx<7;kx++){
          int xx=x+kx-3; if((unsigned)xx>15u) continue;
          acc+=W[ky*7+kx]*AG[ic][yy*16+xx];
        }
      }
    }
    sg[(size_t)(b*2+o)*256+s]=sigmoidf_(acc);
  }
}
__global__ void ga_attn_k(const float* __restrict__ a1s, const float* __restrict__ a2s,
                          const float* __restrict__ sg, const float* __restrict__ cw,
                          const float* __restrict__ cb, float* __restrict__ attn){
  int i=blockIdx.x*blockDim.x+threadIdx.x;
  if(i>=32*64*256) return;
  int s=i&255; int boc=i>>8; int oc=boc&63; int b=boc>>6;
  float s0=sg[(size_t)(b*2+0)*256+s];
  float s1=sg[(size_t)(b*2+1)*256+s];
  const float* A1=a1s+(size_t)b*32*256;
  const float* A2=a2s+(size_t)b*32*256;
  float acc=cb[oc];
  for(int j=0;j<32;j++)
    acc+=cw[oc*32+j]*(A1[j*256+s]*s0+A2[j*256+s]*s1);
  attn[i]=acc;
}
__global__ void ga_proj2_unpool_k(const float* __restrict__ hb, const float* __restrict__ attn,
                                  const float* __restrict__ w, const float* __restrict__ bias,
                                  const unsigned char* __restrict__ idx2, float* __restrict__ out){
  int i=blockIdx.x*blockDim.x+threadIdx.x;
  if(i>=32*64*256) return;
  int s=i&255; int boc=i>>8; int oc=boc&63; int b=boc>>6;
  const float* H=hb+(size_t)b*64*256;
  const float* A=attn+(size_t)b*64*256;
  float acc=bias[oc];
  for(int ic=0;ic<64;ic++) acc+=w[oc*64+ic]*H[ic*256+s]*A[ic*256+s];
  int id=idx2[i];
  int y=s>>4, x=s&15;
  float* O=out+(size_t)boc*1024;
  for(int dy=0;dy<2;dy++)
    for(int dx=0;dx<2;dx++)
      O[(2*y+dy)*32+2*x+dx]=(dy*2+dx==id)?acc:0.f;
}
__global__ void ga_final_k(const float* __restrict__ gaout, const unsigned char* __restrict__ idx1,
                           bf16* __restrict__ ph, bf16* __restrict__ pl,
                           const float* __restrict__ mean, const float* __restrict__ istd){
  int i=blockIdx.x*blockDim.x+threadIdx.x;
  if(i>=32*64*1024) return;
  int s=i&1023; int bc=i>>10; int c=bc&63; int b=bc>>6;
  float v=(gaout[i]-mean[c])*istd[c];
  int id=idx1[i];
  int y=s>>5, x=s&31;
  size_t base=(size_t)(192+c)*131072+b*4096;
  for(int dy=0;dy<2;dy++)
    for(int dx=0;dx<2;dx++){
      float o=(dy*2+dx==id)?v:0.f;
      split_store(o, ph, pl, base+(2*y+dy)*64+2*x+dx);
    }
}

// ---------------- launch ----------------------------------------------------------
extern "C" void kernel_launch(void* const* d_in, const int* in_sizes, int n_in,
                              void* d_out, int out_size) {
  const float* x      =(const float*)d_in[0];
  const float* pa_w1  =(const float*)d_in[1];
  const float* pa_w2  =(const float*)d_in[2];
  const float* la_w   =(const float*)d_in[3];
  const float* mra_h1 =(const float*)d_in[4];
  const float* mra_v1 =(const float*)d_in[5];
  const float* mra_h2 =(const float*)d_in[6];
  const float* mra_v2 =(const float*)d_in[7];
  const float* p1w=(const float*)d_in[8];  const float* p1b=(const float*)d_in[9];
  const float* c0w=(const float*)d_in[10]; const float* c0b=(const float*)d_in[11];
  const float* spw=(const float*)d_in[12]; const float* spb=(const float*)d_in[13];
  const float* c1w=(const float*)d_in[14]; const float* c1b=(const float*)d_in[15];
  const float* c2w=(const float*)d_in[16]; const float* c2b=(const float*)d_in[17];
  const float* cw =(const float*)d_in[18]; const float* cb =(const float*)d_in[19];
  const float* sqw=(const float*)d_in[20]; const float* sqb=(const float*)d_in[21];
  const float* p2w=(const float*)d_in[22]; const float* p2b=(const float*)d_in[23];
  const float* mlp_w1=(const float*)d_in[24];
  const float* mlp_w2=(const float*)d_in[25];
  float* out=(float*)d_out;

  float *tmp,*xm,*gsum,*x4p,*xp,*hb,*a1b,*a2b,*a1s,*a2s,*sigb,*attnb,*gaout,*mean,*istd,*psum,*psq;
  bf16 *ph,*pl,*bh,*bl,*xh,*xl,*wh,*wl;
  unsigned char *idx1,*idx2;
  cudaGetSymbolAddress((void**)&ph,g_ph);   cudaGetSymbolAddress((void**)&pl,g_pl);
  cudaGetSymbolAddress((void**)&bh,g_bh);   cudaGetSymbolAddress((void**)&bl,g_bl);
  cudaGetSymbolAddress((void**)&xh,g_xh);   cudaGetSymbolAddress((void**)&xl,g_xl);
  cudaGetSymbolAddress((void**)&wh,g_wh);   cudaGetSymbolAddress((void**)&wl,g_wl);
  cudaGetSymbolAddress((void**)&psum,g_psum); cudaGetSymbolAddress((void**)&psq,g_psq);
  cudaGetSymbolAddress((void**)&tmp,g_tmp); cudaGetSymbolAddress((void**)&xm,g_xm);
  cudaGetSymbolAddress((void**)&gsum,g_gsum); cudaGetSymbolAddress((void**)&x4p,g_x4p);
  cudaGetSymbolAddress((void**)&xp,g_xp);   cudaGetSymbolAddress((void**)&hb,g_hb);
  cudaGetSymbolAddress((void**)&a1b,g_a1b); cudaGetSymbolAddress((void**)&a2b,g_a2b);
  cudaGetSymbolAddress((void**)&a1s,g_a1s); cudaGetSymbolAddress((void**)&a2s,g_a2s);
  cudaGetSymbolAddress((void**)&sigb,g_sigb); cudaGetSymbolAddress((void**)&attnb,g_attnb);
  cudaGetSymbolAddress((void**)&gaout,g_gaout);
  cudaGetSymbolAddress((void**)&mean,g_mean); cudaGetSymbolAddress((void**)&istd,g_istd);
  cudaGetSymbolAddress((void**)&idx1,g_idx1); cudaGetSymbolAddress((void**)&idx2,g_idx2);

  const int T=256;
  const int W_PA1=0, W_PA2=16384, W_LA=32768, W_FC1=69632, W_FC2=200704;

  static cudaStream_t s1=0,s2=0,s3=0;
  static cudaEvent_t evRoot=0,evSplit=0,ev1=0,ev2=0,ev3=0;
  if(!s1){
    cudaStreamCreateWithFlags(&s1,cudaStreamNonBlocking);
    cudaStreamCreateWithFlags(&s2,cudaStreamNonBlocking);
    cudaStreamCreateWithFlags(&s3,cudaStreamNonBlocking);
    cudaEventCreateWithFlags(&evRoot,cudaEventDisableTiming);
    cudaEventCreateWithFlags(&evSplit,cudaEventDisableTiming);
    cudaEventCreateWithFlags(&ev1,cudaEventDisableTiming);
    cudaEventCreateWithFlags(&ev2,cudaEventDisableTiming);
    cudaEventCreateWithFlags(&ev3,cudaEventDisableTiming);
    cudaFuncSetAttribute((const void*)tg2_k<128,true,false,BSCopy,EpSplitStore>,
                         cudaFuncAttributeMaxDynamicSharedMemorySize, SMEM128);
    cudaFuncSetAttribute((const void*)tg2_k<64,false,true,BSCopy,EpGateMulSplit>,
                         cudaFuncAttributeMaxDynamicSharedMemorySize, SMEM64);
    cudaFuncSetAttribute((const void*)tg2_k<64,true,false,BSIm2col,EpStore>,
                         cudaFuncAttributeMaxDynamicSharedMemorySize, SMEM64);
    cudaFuncSetAttribute((const void*)tg2_k<128,false,true,BSCopy,EpResidual>,
                         cudaFuncAttributeMaxDynamicSharedMemorySize, SMEM128);
  }

  cudaEventRecord(evRoot, 0);
  cudaStreamWaitEvent(s2, evRoot, 0);
  cudaStreamWaitEvent(s3, evRoot, 0);

  wsplit_all_k<<<1296,T>>>(pa_w1,pa_w2,la_w,mlp_w1,mlp_w2, wh, wl);
  xsplit_k<<<65536,T>>>(x, xh, xl);
  cudaEventRecord(evSplit, 0);
  cudaStreamWaitEvent(s1, evSplit, 0);

  tg2_k<128,true,false><<<dim3(2,1024),256,SMEM128>>>(wh+W_PA1, wl+W_PA1, 64,
      BSCopy{xh,xl}, EpSplitStore{bh,bl}, psum, psq, 256, nullptr, nullptr);
  bn_fin_k<<<256,T>>>(psum,psq,256, mean+0, istd+0);
  tg2_k<64,false,true><<<dim3(1,1024),256,SMEM64>>>(wh+W_PA2, wl+W_PA2, 256,
      BSCopy{bh,bl}, EpGateMulSplit{ph,pl,x}, nullptr,nullptr,0, mean+0, istd+0);

  tg2_k<64,true,false><<<dim3(1,1024),256,SMEM64,s1>>>(wh+W_LA, wl+W_LA, 576,
      BSIm2col{xh+(size_t)64*131072, xl+(size_t)64*131072}, EpStore{tmp,64,0},
      psum+262144, psq+262144, 64, nullptr, nullptr);
  bn_fin_k<<<64,T,0,s1>>>(psum+262144,psq+262144,64, mean+256, istd+256);
  la_apply_k<<<32768,T,0,s1>>>(tmp, ph, pl, mean+256, istd+256);

  blurpool_k<<<3872,T,0,s2>>>(x, xm);
  mra_strips_k<<<3872,T,0,s2>>>(mra_h1, mra_v1, mra_h2, mra_v2, xm, gsum);
  bn_stats_k<<<64,T,0,s2>>>(gsum,64,484, mean+320, istd+320);
  mra_apply_k<<<32768,T,0,s2>>>(x, gsum, ph, pl, mean+320, istd+320);

  pool2_k<<<8192,T,0,s3>>>(x, 256L*4096L, 192, 64, x4p, idx1, 32*64*1024);
  pool2_k<<<2048,T,0,s3>>>(x4p, 64L*1024L, 0, 32, xp, idx2, 32*64*256);
  ga_proj1_k<<<2048,T,0,s3>>>(xp, p1w, p1b, hb);
  ga_dw_k<<<2048,T,0,s3>>>(hb, c0w, c0b, spw, spb, a1b, a2b);
  ga_c1c2_k<<<2048,T,0,s3>>>(a1b, a2b, c1w, c1b, c2w, c2b, a1s, a2s);
  ga_aggsq_k<<<32,T,0,s3>>>(a1s, a2s, sqw, sqb, sigb);
  ga_attn_k<<<2048,T,0,s3>>>(a1s, a2s, sigb, cw, cb, attnb);
  ga_proj2_unpool_k<<<2048,T,0,s3>>>(hb, attnb, p2w, p2b, idx2, gaout);
  bn_stats_k<<<64,T,0,s3>>>(gaout,64,1024, mean+384, istd+384);
  ga_final_k<<<8192,T,0,s3>>>(gaout, idx1, ph, pl, mean+384, istd+384);

  cudaEventRecord(ev1,s1); cudaEventRecord(ev2,s2); cudaEventRecord(ev3,s3);
  cudaStreamWaitEvent(0, ev1, 0);
  cudaStreamWaitEvent(0, ev2, 0);
  cudaStreamWaitEvent(0, ev3, 0);

  tg2_k<128,true,false><<<dim3(4,1024),256,SMEM128>>>(wh+W_FC1, wl+W_FC1, 256,
      BSCopy{ph,pl}, EpSplitStore{bh,bl}, psum, psq, 512, nullptr, nullptr);
  bn_fin_k<<<512,T>>>(psum,psq,512, mean+448, istd+448);
  tg2_k<128,false,true><<<dim3(2,1024),256,SMEM128>>>(wh+W_FC2, wl+W_FC2, 512,
      BSCopy{bh,bl}, EpResidual{out,x}, nullptr,nullptr,0, mean+448, istd+448);
}

// round 14
// speedup vs baseline: 1.1163x; 1.1163x over previous
#include <cuda_runtime.h>
#include <cuda_bf16.h>
#include <math.h>

#define EPSF 1e-5f
typedef __nv_bfloat16 bf16;

// ---------------- scratch -----------------------------------------------------
__device__ bf16  g_ph[33554432];
__device__ bf16  g_pl[33554432];
__device__ bf16  g_bh[67108864];
__device__ bf16  g_bl[67108864];
__device__ bf16  g_xh[16777216];
__device__ bf16  g_xl[16777216];
__device__ bf16  g_wh[524288];
__device__ bf16  g_wl[524288];
__device__ float g_psum[524288];
__device__ float g_psq[524288];
__device__ float g_tmp[8388608];
__device__ float g_xm[32*64*484];
__device__ float g_gsum[32*64*484];
__device__ float g_x4p[32*64*1024];
__device__ unsigned char g_idx1[32*64*1024];
__device__ float g_xp[32*64*256];
__device__ unsigned char g_idx2[32*64*256];
__device__ float g_hb[32*64*256];
__device__ float g_a1b[32*64*256];
__device__ float g_a2b[32*64*256];
__device__ float g_a1s[32*32*256];
__device__ float g_a2s[32*32*256];
__device__ float g_sigb[32*2*256];
__device__ float g_attnb[32*64*256];
__device__ float g_gaout[32*64*1024];
__device__ float g_mean[1024];
__device__ float g_istd[1024];

__device__ __forceinline__ float sigmoidf_(float v){ return 1.0f/(1.0f+expf(-v)); }
__device__ __forceinline__ void split_store(float v, bf16* h, bf16* l, size_t i){
  bf16 hh=__float2bfloat16(v);
  h[i]=hh; l[i]=__float2bfloat16(v-__bfloat162float(hh));
}
__device__ __forceinline__ void cpa16(void* s, const void* g){
  unsigned sa=(unsigned)__cvta_generic_to_shared(s);
  asm volatile("cp.async.ca.shared.global [%0],[%1],16;"::"r"(sa),"l"(g));
}
__device__ __forceinline__ void ldmx4(unsigned* r, const bf16* p){
  unsigned a=(unsigned)__cvta_generic_to_shared(p);
  asm volatile("ldmatrix.sync.aligned.m8n8.x4.shared.b16 {%0,%1,%2,%3},[%4];"
   :"=r"(r[0]),"=r"(r[1]),"=r"(r[2]),"=r"(r[3]):"r"(a));
}
__device__ __forceinline__ void ldmx4t(unsigned* r, const bf16* p){
  unsigned a=(unsigned)__cvta_generic_to_shared(p);
  asm volatile("ldmatrix.sync.aligned.m8n8.x4.trans.shared.b16 {%0,%1,%2,%3},[%4];"
   :"=r"(r[0]),"=r"(r[1]),"=r"(r[2]),"=r"(r[3]):"r"(a));
}
__device__ __forceinline__ void mma16816(float* c,const unsigned* a,const unsigned* b){
  asm volatile("mma.sync.aligned.m16n8k16.row.col.f32.bf16.bf16.f32 "
    "{%0,%1,%2,%3},{%4,%5,%6,%7},{%8,%9},{%0,%1,%2,%3};"
    :"+f"(c[0]),"+f"(c[1]),"+f"(c[2]),"+f"(c[3])
    :"r"(a[0]),"r"(a[1]),"r"(a[2]),"r"(a[3]),"r"(b[0]),"r"(b[1]));
}

// ---------------- B stagers (BK=16) --------------------------------------------
#define PBP 136
struct BSCopy {
  const bf16 *bh, *bl;
  __device__ __forceinline__ void stage(bf16* Bh, bf16* Bl, int k0, int n0, int tid) const {
    int k=tid>>4, nc=(tid&15)*8;
    cpa16(&Bh[k*PBP+nc], bh+(size_t)(k0+k)*131072+n0+nc);
    cpa16(&Bl[k*PBP+nc], bl+(size_t)(k0+k)*131072+n0+nc);
  }
};
struct BSIm2col {
  const bf16 *xh, *xl;
  __device__ __forceinline__ void stage(bf16* Bh, bf16* Bl, int k0, int n0, int tid) const {
#pragma unroll
    for(int it=0;it<8;it++){
      int id=it*256+tid; int k=id>>7, n=id&127;
      int kk=k0+k;
      int ic=kk/9; int t=kk-ic*9; int dy=t/3-1, dx=t%3-1;
      int na=n0+n; int p=na&4095;
      int h=(p>>6)+dy, w=(p&63)+dx;
      bf16 vh, vl;
      if((unsigned)h>63u||(unsigned)w>63u){ vh=__float2bfloat16(0.f); vl=vh; }
      else{
        size_t gi=(size_t)ic*131072+(size_t)(na&~4095)+h*64+w;
        vh=xh[gi]; vl=xl[gi];
      }
      Bh[k*PBP+n]=vh; Bl[k*PBP+n]=vl;
    }
  }
};

// ---------------- epilogues ---------------------------------------------------
struct EpStore {
  float* o; int MC; int oc0;
  __device__ __forceinline__ void operator()(int m,int n,float a) const {
    int b=n>>12,p=n&4095;
    o[((size_t)(b*MC+oc0+m)<<12)+p]=a;
  }
};
struct EpSplitStore {
  bf16 *oh,*ol;
  __device__ __forceinline__ void operator()(int m,int n,float a) const {
    split_store(a, oh, ol, (size_t)m*131072+n);
  }
};
struct EpGateMulSplit {
  bf16 *ph,*pl; const float* x;
  __device__ __forceinline__ void operator()(int m,int n,float a) const {
    int b=n>>12,p=n&4095;
    float v=x[((size_t)(b*256+m)<<12)+p]*sigmoidf_(a);
    split_store(v, ph, pl, (size_t)m*131072+n);
  }
};
struct EpResidual {
  float* o; const float* x;
  __device__ __forceinline__ void operator()(int m,int n,float a) const {
    int b=n>>12,p=n&4095;
    size_t i=((size_t)(b*256+m)<<12)+p;
    o[i]=x[i]+a;
  }
};

// ------- legacy tensor-core GEMM (R12 config: BK=16, 3-pass), BNORM own-chunk ---
template<int BM,bool STATS,bool BNORMOWN,class BS,class EP>
__global__ __launch_bounds__(256,2)
void tg2_k(const bf16* __restrict__ wh, const bf16* __restrict__ wl,
           int K, BS bs, EP ep,
           float* __restrict__ psum, float* __restrict__ psq, int C,
           const float* __restrict__ mean, const float* __restrict__ istd){
  constexpr int PA=24;
  constexpr int WTM=BM/2, MI=WTM/16;
  __shared__ __align__(16) bf16 Ah[2][BM*PA], Al[2][BM*PA];
  __shared__ __align__(16) bf16 Bh[2][16*PBP], Bl[2][16*PBP];
  __shared__ float sS4[4*BM], sQ4[4*BM];
  const int tid=threadIdx.x;
  const int warp=tid>>5, lane=tid&31;
  const int wm=warp>>2, wn=warp&3;
  const int m0=blockIdx.x*BM, n0=blockIdx.y*128;
  float c[MI][4][4];
#pragma unroll
  for(int i=0;i<MI;i++)
#pragma unroll
    for(int j=0;j<4;j++)
#pragma unroll
      for(int q=0;q<4;q++) c[i][j][q]=0.f;
  auto stageA=[&](int buf,int k0){
    for(int id=tid; id<BM*2; id+=256){
      int m=id>>1, kc=(id&1)*8;
      cpa16(&Ah[buf][m*PA+kc], wh+(size_t)(m0+m)*K+k0+kc);
      cpa16(&Al[buf][m*PA+kc], wl+(size_t)(m0+m)*K+k0+kc);
    }
  };
  const int KT=K/16;
  stageA(0,0);
  bs.stage(Bh[0],Bl[0],0,n0,tid);
  asm volatile("cp.async.commit_group;");
  int buf=0;
  for(int kt=0;kt<KT;kt++){
    if(kt+1<KT){
      stageA(buf^1,(kt+1)*16);
      bs.stage(Bh[buf^1],Bl[buf^1],(kt+1)*16,n0,tid);
      asm volatile("cp.async.commit_group;");
      asm volatile("cp.async.wait_group 1;");
    } else {
      asm volatile("cp.async.wait_group 0;");
    }
    if(BNORMOWN){
      // normalize exactly the chunk this thread staged (BSCopy mapping);
      // visible after wait_group -> no second barrier needed.
      int k=tid>>4, nc=(tid&15)*8;
      float mm=__ldg(&mean[kt*16+k]), is=__ldg(&istd[kt*16+k]);
      bf16* bph=&Bh[buf][k*PBP+nc];
      bf16* bpl=&Bl[buf][k*PBP+nc];
#pragma unroll
      for(int e=0;e<8;e++){
        float v=__bfloat162float(bph[e])+__bfloat162float(bpl[e]);
        v=(v-mm)*is; v=v>0.f?v:0.f;
        bf16 hh=__float2bfloat16(v);
        bph[e]=hh; bpl[e]=__float2bfloat16(v-__bfloat162float(hh));
      }
    }
    __syncthreads();
    // ---- compute tile: 3 passes, each pass = independent MMAs -----------------
    const int arow=lane&15, acol=(lane>>4)<<3;
    unsigned a4[MI][4];
    unsigned b4h[2][4], b4l[2][4];
#pragma unroll
    for(int np=0;np<2;np++){
      int rb=(lane&15)*PBP+wn*32+np*16+((lane>>4)<<3);
      ldmx4t(b4h[np], &Bh[buf][rb]);
      ldmx4t(b4l[np], &Bl[buf][rb]);
    }
#pragma unroll
    for(int mi=0;mi<MI;mi++)
      ldmx4(a4[mi], &Ah[buf][(wm*WTM+mi*16+arow)*PA+acol]);
#pragma unroll
    for(int np=0;np<2;np++)
#pragma unroll
      for(int t2=0;t2<2;t2++)
#pragma unroll
        for(int mi=0;mi<MI;mi++)
          mma16816(c[mi][np*2+t2], a4[mi], &b4h[np][t2*2]);
#pragma unroll
    for(int np=0;np<2;np++)
#pragma unroll
      for(int t2=0;t2<2;t2++)
#pragma unroll
        for(int mi=0;mi<MI;mi++)
          mma16816(c[mi][np*2+t2], a4[mi], &b4l[np][t2*2]);
#pragma unroll
    for(int mi=0;mi<MI;mi++)
      ldmx4(a4[mi], &Al[buf][(wm*WTM+mi*16+arow)*PA+acol]);
#pragma unroll
    for(int np=0;np<2;np++)
#pragma unroll
      for(int t2=0;t2<2;t2++)
#pragma unroll
        for(int mi=0;mi<MI;mi++)
          mma16816(c[mi][np*2+t2], a4[mi], &b4h[np][t2*2]);
    __syncthreads();
    buf^=1;
  }
  if(STATS){
#pragma unroll
    for(int mi=0;mi<MI;mi++){
      float s1=0.f,q1=0.f,s2=0.f,q2=0.f;
#pragma unroll
      for(int ni=0;ni<4;ni++){
        s1+=c[mi][ni][0]+c[mi][ni][1];
        q1+=c[mi][ni][0]*c[mi][ni][0]+c[mi][ni][1]*c[mi][ni][1];
        s2+=c[mi][ni][2]+c[mi][ni][3];
        q2+=c[mi][ni][2]*c[mi][ni][2]+c[mi][ni][3]*c[mi][ni][3];
      }
#pragma unroll
      for(int off=1;off<4;off<<=1){
        s1+=__shfl_xor_sync(0xffffffffu,s1,off);
        q1+=__shfl_xor_sync(0xffffffffu,q1,off);
        s2+=__shfl_xor_sync(0xffffffffu,s2,off);
        q2+=__shfl_xor_sync(0xffffffffu,q2,off);
      }
      if((lane&3)==0){
        int mr=wm*WTM+mi*16+(lane>>2);
        sS4[wn*BM+mr]=s1; sQ4[wn*BM+mr]=q1;
        sS4[wn*BM+mr+8]=s2; sQ4[wn*BM+mr+8]=q2;
      }
    }
    __syncthreads();
    for(int i=tid;i<BM;i+=256){
      float s=sS4[i]+sS4[BM+i]+sS4[2*BM+i]+sS4[3*BM+i];
      float q=sQ4[i]+sQ4[BM+i]+sQ4[2*BM+i]+sQ4[3*BM+i];
      psum[(size_t)blockIdx.y*C+m0+i]=s;
      psq [(size_t)blockIdx.y*C+m0+i]=q;
    }
  }
  const int r=lane>>2, q=lane&3;
#pragma unroll
  for(int mi=0;mi<MI;mi++)
#pragma unroll
    for(int ni=0;ni<4;ni++){
      int m=m0+wm*WTM+mi*16+r;
      int n=n0+wn*32+ni*8+2*q;
      ep(m,   n,   c[mi][ni][0]);
      ep(m,   n+1, c[mi][ni][1]);
      ep(m+8, n,   c[mi][ni][2]);
      ep(m+8, n+1, c[mi][ni][3]);
    }
}

// ---------------- stats finalize -----------------------------------------------
__global__ void bn_fin_k(const float* __restrict__ psum, const float* __restrict__ psq,
                         int C, float* __restrict__ mean, float* __restrict__ istd){
  int c=blockIdx.x;
  float s=0.f,q=0.f;
  for(int i=threadIdx.x;i<1024;i+=256){ s+=psum[(size_t)i*C+c]; q+=psq[(size_t)i*C+c]; }
  __shared__ float sh[256], sh2[256];
  sh[threadIdx.x]=s; sh2[threadIdx.x]=q; __syncthreads();
  for(int o=128;o>0;o>>=1){
    if(threadIdx.x<o){ sh[threadIdx.x]+=sh[threadIdx.x+o]; sh2[threadIdx.x]+=sh2[threadIdx.x+o]; }
    __syncthreads();
  }
  if(threadIdx.x==0){
    float m=sh[0]*(1.f/131072.f);
    float v=sh2[0]*(1.f/131072.f)-m*m;
    mean[c]=m; istd[c]=rsqrtf(v+EPSF);
  }
}

// ---------------- split kernels ---------------------------------------------------
__global__ void wsplit_all_k(const float* __restrict__ w1,const float* __restrict__ w2,
                             const float* __restrict__ w3,const float* __restrict__ w4,
                             const float* __restrict__ w5,
                             bf16* __restrict__ h, bf16* __restrict__ l){
  int i=blockIdx.x*blockDim.x+threadIdx.x;
  if(i>=331776) return;
  const float* src; int off;
  if(i<16384){src=w1;off=0;}
  else if(i<32768){src=w2;off=16384;}
  else if(i<69632){src=w3;off=32768;}
  else if(i<200704){src=w4;off=69632;}
  else {src=w5;off=200704;}
  split_store(src[i-off], h, l, i);
}
__global__ void xsplit_k(const float* __restrict__ x, bf16* __restrict__ xh,
                         bf16* __restrict__ xl){
  int i=blockIdx.x*blockDim.x+threadIdx.x;
  if(i>=32*128*4096) return;
  int p=i&4095; int bc=i>>12; int ch=bc&127; int b=bc>>7;
  float v=x[((size_t)(b*256+ch)<<12)+p];
  split_store(v, xh, xl, (size_t)ch*131072+b*4096+p);
}
__global__ void bn_stats_k(const float* __restrict__ d, int C, int S,
                           float* __restrict__ mean, float* __restrict__ istd){
  int c=blockIdx.x;
  double s=0.0,s2=0.0;
  for(int b=0;b<32;b++){
    const float* P=d+(size_t)(b*C+c)*S;
    for(int off=threadIdx.x;off<S;off+=256){
      float v=P[off]; s+=(double)v; s2+=(double)v*(double)v;
    }
  }
  __shared__ double sh[256], sh2[256];
  sh[threadIdx.x]=s; sh2[threadIdx.x]=s2; __syncthreads();
  for(int o=128;o>0;o>>=1){
    if(threadIdx.x<o){ sh[threadIdx.x]+=sh[threadIdx.x+o]; sh2[threadIdx.x]+=sh2[threadIdx.x+o]; }
    __syncthreads();
  }
  if(threadIdx.x==0){
    double N=32.0*(double)S;
    double m=sh[0]/N, v=sh2[0]/N-m*m;
    mean[c]=(float)m; istd[c]=rsqrtf((float)v+EPSF);
  }
}
__global__ void la_apply_k(const float* __restrict__ t, bf16* __restrict__ ph,
                           bf16* __restrict__ pl,
                           const float* __restrict__ mean, const float* __restrict__ istd){
  int i=blockIdx.x*blockDim.x+threadIdx.x;
  if(i>=32*64*4096) return;
  int p=i&4095; int bc=i>>12; int c=bc&63; int b=bc>>6;
  float v=(t[i]-mean[c])*istd[c];
  v=v>0.f?v:0.f;
  split_store(v, ph, pl, (size_t)(64+c)*131072+b*4096+p);
}
__global__ void blurpool_k(const float* __restrict__ x, float* __restrict__ xm){
  int i=blockIdx.x*blockDim.x+threadIdx.x;
  if(i>=32*64*484) return;
  int s=i%484; int bc=i/484; int c=bc&63; int b=bc>>6;
  const float* X=x+(((size_t)(b*256+128+c))<<12);
  int oh=s/22, ow=s%22;
  const float f0[4]={1.f,3.f,3.f,1.f};
  float acc=0.f;
  for(int iy=0;iy<4;iy++){
    int u=3*oh+iy-1; u=u<0?-u:u; u=u>63?126-u:u;
    float fy=f0[iy];
    for(int ix=0;ix<4;ix++){
      int v=3*ow+ix-1; v=v<0?-v:v; v=v>63?126-v:v;
      float m=-3.4e38f;
      for(int dy=-1;dy<=1;dy++){
        int yy=u+dy; if((unsigned)yy>63u) continue;
        for(int dx=-1;dx<=1;dx++){
          int xx=v+dx; if((unsigned)xx>63u) continue;
          float vv=X[yy*64+xx]; m=vv>m?vv:m;
        }
      }
      acc+=fy*f0[ix]*m;
    }
  }
  xm[i]=acc*(1.f/64.f);
}
__global__ void mra_strips_k(const float* __restrict__ wh1, const float* __restrict__ wv1,
                             const float* __restrict__ wh2, const float* __restrict__ wv2,
                             const float* __restrict__ xm, float* __restrict__ gsum){
  int i=blockIdx.x*blockDim.x+threadIdx.x;
  if(i>=32*64*484) return;
  int s=i%484; int bc=i/484; int c=bc&63;
  int r=s/22, cc=s%22;
  const float* X=xm+(size_t)bc*484;
  const float* W1=wh1+c*33; const float* V1=wv1+c*33;
  const float* W2=wh2+c*33; const float* V2=wv2+c*33;
  float acc=0.f;
  for(int ky=0;ky<11;ky++){
    int y=r+ky-5; if((unsigned)y>=22u) continue;
    for(int kx=0;kx<3;kx++){
      int x2=cc+kx-1; if((unsigned)x2>=22u) continue;
      acc+=W1[ky*3+kx]*X[y*22+x2];
    }
  }
  for(int ky=0;ky<3;ky++){
    int y=r+ky-1; if((unsigned)y>=22u) continue;
    for(int kx=0;kx<11;kx++){
      int x2=cc+kx-5; if((unsigned)x2>=22u) continue;
      acc+=V1[ky*11+kx]*X[y*22+x2];
    }
  }
  {
    int i2=r*44+cc; int R=i2/43, C=i2-43*R;
    for(int ky=0;ky<11;ky++){
      int RR=R+ky-5; if((unsigned)RR>=22u) continue;
      for(int kx=0;kx<3;kx++){
        int CC=C+kx-1; if((unsigned)CC>=43u) continue;
        int j=RR*43+CC; int q=j/44, m=j-44*q;
        if(m<22) acc+=W2[ky*3+kx]*X[q*22+m];
      }
    }
  }
  {
    int j=cc*44+r; int b2=j/43, a2=j-43*b2;
    for(int ky=0;ky<3;ky++){
      int RR=a2+ky-1; if((unsigned)RR>=43u) continue;
      for(int kx=0;kx<11;kx++){
        int CC=b2+kx-5; if((unsigned)CC>=22u) continue;
        int j2=CC*43+RR; int q=j2/44, m=j2-44*q;
        if(m<22) acc+=V2[ky*11+kx]*X[m*22+q];
      }
    }
  }
  gsum[i]=acc;
}
__global__ void mra_apply_k(const float* __restrict__ x, const float* __restrict__ gsum,
                            bf16* __restrict__ ph, bf16* __restrict__ pl,
                            const float* __restrict__ mean, const float* __restrict__ istd){
  int i=blockIdx.x*blockDim.x+threadIdx.x;
  if(i>=32*64*4096) return;
  int p=i&4095, bc=i>>12, c=bc&63, b=bc>>6;
  int h=p>>6, w=p&63;
  int ri=(h*22)>>6, ci=(w*22)>>6;
  float g=gsum[(size_t)bc*484+ri*22+ci];
  g=sigmoidf_((g-mean[c])*istd[c]);
  float v=x[((size_t)(b*256+128+c)<<12)+p]*g;
  split_store(v, ph, pl, (size_t)(128+c)*131072+b*4096+p);
}
__global__ void pool2_k(const float* __restrict__ in, long bstride, int c0, int inW,
                        float* __restrict__ out, unsigned char* __restrict__ idx, int total){
  int i=blockIdx.x*blockDim.x+threadIdx.x;
  if(i>=total) return;
  int outW=inW>>1; int os=outW*outW;
  int s=i%os; int bc=i/os; int b=bc>>6, c=bc&63;
  int oh=s/outW, ow=s-oh*outW;
  const float* P=in+(size_t)b*bstride+(size_t)(c0+c)*inW*inW;
  float v0=P[(2*oh)*inW+2*ow],   v1=P[(2*oh)*inW+2*ow+1];
  float v2=P[(2*oh+1)*inW+2*ow], v3=P[(2*oh+1)*inW+2*ow+1];
  float best=v0; int bi=0;
  if(v1>best){best=v1;bi=1;}
  if(v2>best){best=v2;bi=2;}
  if(v3>best){best=v3;bi=3;}
  out[i]=best; idx[i]=(unsigned char)bi;
}
__global__ void ga_proj1_k(const float* __restrict__ xp, const float* __restrict__ w,
                           const float* __restrict__ bias, float* __restrict__ hb){
  int i=blockIdx.x*blockDim.x+threadIdx.x;
  if(i>=32*64*256) return;
  int s=i&255; int boc=i>>8; int oc=boc&63; int b=boc>>6;
  const float* X=xp+(size_t)b*64*256;
  float acc=bias[oc];
  for(int ic=0;ic<64;ic++) acc+=w[oc*64+ic]*X[ic*256+s];
  hb[i]=acc>0.f?acc:0.f;
}
__global__ void ga_dw_k(const float* __restrict__ hb,
                        const float* __restrict__ c0w, const float* __restrict__ c0b,
                        const float* __restrict__ spw, const float* __restrict__ spb,
                        float* __restrict__ a1, float* __restrict__ a2){
  int bc=blockIdx.x; int c=bc&63;
  int s=threadIdx.x;
  int y=s>>4, x=s&15;
  __shared__ float A1[256];
  const float* H=hb+(size_t)bc*256;
  float acc=c0b[c];
  for(int ky=0;ky<5;ky++){
    int yy=y+ky-2; if((unsigned)yy>15u) continue;
    for(int kx=0;kx<5;kx++){
      int xx=x+kx-2; if((unsigned)xx>15u) continue;
      acc+=c0w[c*25+ky*5+kx]*H[yy*16+xx];
    }
  }
  A1[s]=acc; a1[(size_t)bc*256+s]=acc;
  __syncthreads();
  float acc2=spb[c];
  for(int ky=0;ky<7;ky++){
    int yy=y+3*ky-9; if((unsigned)yy>15u) continue;
    for(int kx=0;kx<7;kx++){
      int xx=x+3*kx-9; if((unsigned)xx>15u) continue;
      acc2+=spw[c*49+ky*7+kx]*A1[yy*16+xx];
    }
  }
  a2[(size_t)bc*256+s]=acc2;
}
__global__ void ga_c1c2_k(const float* __restrict__ a1, const float* __restrict__ a2,
                          const float* __restrict__ c1w, const float* __restrict__ c1b,
                          const float* __restrict__ c2w, const float* __restrict__ c2b,
                          float* __restrict__ a1s, float* __restrict__ a2s){
  int i=blockIdx.x*blockDim.x+threadIdx.x;
  if(i>=2*32*32*256) return;
  int which=i/(32*32*256); int rr=i-which*(32*32*256);
  int s=rr&255; int bj=rr>>8; int j=bj&31; int b=bj>>5;
  const float* src=which?a2:a1;
  const float* W=which?c2w:c1w;
  const float* Bb=which?c2b:c1b;
  const float* S=src+(size_t)b*64*256;
  float acc=Bb[j];
  for(int ic=0;ic<64;ic++) acc+=W[j*64+ic]*S[ic*256+s];
  (which?a2s:a1s)[(size_t)(b*32+j)*256+s]=acc;
}
__global__ void ga_aggsq_k(const float* __restrict__ a1s, const float* __restrict__ a2s,
                           const float* __restrict__ sqw, const float* __restrict__ sqb,
                           float* __restrict__ sg){
  int b=blockIdx.x; int s=threadIdx.x;
  __shared__ float AG[2][256];
  const float* A1=a1s+(size_t)b*32*256;
  const float* A2=a2s+(size_t)b*32*256;
  float sum=0.f, mx=-3.4e38f;
  for(int j=0;j<32;j++){
    float v1=A1[j*256+s]; sum+=v1; mx=v1>mx?v1:mx;
    float v2=A2[j*256+s]; sum+=v2; mx=v2>mx?v2:mx;
  }
  AG[0][s]=sum*(1.f/64.f); AG[1][s]=mx;
  __syncthreads();
  int y=s>>4, x=s&15;
  for(int o=0;o<2;o++){
    float acc=sqb[o];
    for(int ic=0;ic<2;ic++){
      const float* W=sqw+((o*2+ic)*49);
      for(int ky=0;ky<7;ky++){
        int yy=y+ky-3; if((unsigned)yy>15u) continue;
        for(int kx=0;kx<7;kx++){
          int xx=x+kx-3; if((unsigned)xx>15u) continue;
          acc+=W[ky*7+kx]*AG[ic][yy*16+xx];
        }
      }
    }
    sg[(size_t)(b*2+o)*256+s]=sigmoidf_(acc);
  }
}
__global__ void ga_attn_k(const float* __restrict__ a1s, const float* __restrict__ a2s,
                          const float* __restrict__ sg, const float* __restrict__ cw,
                          const float* __restrict__ cb, float* __restrict__ attn){
  int i=blockIdx.x*blockDim.x+threadIdx.x;
  if(i>=32*64*256) return;
  int s=i&255; int boc=i>>8; int oc=boc&63; int b=boc>>6;
  float s0=sg[(size_t)(b*2+0)*256+s];
  float s1=sg[(size_t)(b*2+1)*256+s];
  const float* A1=a1s+(size_t)b*32*256;
  const float* A2=a2s+(size_t)b*32*256;
  float acc=cb[oc];
  for(int j=0;j<32;j++)
    acc+=cw[oc*32+j]*(A1[j*256+s]*s0+A2[j*256+s]*s1);
  attn[i]=acc;
}
__global__ void ga_proj2_unpool_k(const float* __restrict__ hb, const float* __restrict__ attn,
                                  const float* __restrict__ w, const float* __restrict__ bias,
                                  const unsigned char* __restrict__ idx2, float* __restrict__ out){
  int i=blockIdx.x*blockDim.x+threadIdx.x;
  if(i>=32*64*256) return;
  int s=i&255; int boc=i>>8; int oc=boc&63; int b=boc>>6;
  const float* H=hb+(size_t)b*64*256;
  const float* A=attn+(size_t)b*64*256;
  float acc=bias[oc];
  for(int ic=0;ic<64;ic++) acc+=w[oc*64+ic]*H[ic*256+s]*A[ic*256+s];
  int id=idx2[i];
  int y=s>>4, x=s&15;
  float* O=out+(size_t)boc*1024;
  for(int dy=0;dy<2;dy++)
    for(int dx=0;dx<2;dx++)
      O[(2*y+dy)*32+2*x+dx]=(dy*2+dx==id)?acc:0.f;
}
__global__ void ga_final_k(const float* __restrict__ gaout, const unsigned char* __restrict__ idx1,
                           bf16* __restrict__ ph, bf16* __restrict__ pl,
                           const float* __restrict__ mean, const float* __restrict__ istd){
  int i=blockIdx.x*blockDim.x+threadIdx.x;
  if(i>=32*64*1024) return;
  int s=i&1023; int bc=i>>10; int c=bc&63; int b=bc>>6;
  float v=(gaout[i]-mean[c])*istd[c];
  int id=idx1[i];
  int y=s>>5, x=s&31;
  size_t base=(size_t)(192+c)*131072+b*4096;
  for(int dy=0;dy<2;dy++)
    for(int dx=0;dx<2;dx++){
      float o=(dy*2+dx==id)?v:0.f;
      split_store(o, ph, pl, base+(2*y+dy)*64+2*x+dx);
    }
}

// ---------------- launch ----------------------------------------------------------
extern "C" void kernel_launch(void* const* d_in, const int* in_sizes, int n_in,
                              void* d_out, int out_size) {
  const float* x      =(const float*)d_in[0];
  const float* pa_w1  =(const float*)d_in[1];
  const float* pa_w2  =(const float*)d_in[2];
  const float* la_w   =(const float*)d_in[3];
  const float* mra_h1 =(const float*)d_in[4];
  const float* mra_v1 =(const float*)d_in[5];
  const float* mra_h2 =(const float*)d_in[6];
  const float* mra_v2 =(const float*)d_in[7];
  const float* p1w=(const float*)d_in[8];  const float* p1b=(const float*)d_in[9];
  const float* c0w=(const float*)d_in[10]; const float* c0b=(const float*)d_in[11];
  const float* spw=(const float*)d_in[12]; const float* spb=(const float*)d_in[13];
  const float* c1w=(const float*)d_in[14]; const float* c1b=(const float*)d_in[15];
  const float* c2w=(const float*)d_in[16]; const float* c2b=(const float*)d_in[17];
  const float* cw =(const float*)d_in[18]; const float* cb =(const float*)d_in[19];
  const float* sqw=(const float*)d_in[20]; const float* sqb=(const float*)d_in[21];
  const float* p2w=(const float*)d_in[22]; const float* p2b=(const float*)d_in[23];
  const float* mlp_w1=(const float*)d_in[24];
  const float* mlp_w2=(const float*)d_in[25];
  float* out=(float*)d_out;

  float *tmp,*xm,*gsum,*x4p,*xp,*hb,*a1b,*a2b,*a1s,*a2s,*sigb,*attnb,*gaout,*mean,*istd,*psum,*psq;
  bf16 *ph,*pl,*bh,*bl,*xh,*xl,*wh,*wl;
  unsigned char *idx1,*idx2;
  cudaGetSymbolAddress((void**)&ph,g_ph);   cudaGetSymbolAddress((void**)&pl,g_pl);
  cudaGetSymbolAddress((void**)&bh,g_bh);   cudaGetSymbolAddress((void**)&bl,g_bl);
  cudaGetSymbolAddress((void**)&xh,g_xh);   cudaGetSymbolAddress((void**)&xl,g_xl);
  cudaGetSymbolAddress((void**)&wh,g_wh);   cudaGetSymbolAddress((void**)&wl,g_wl);
  cudaGetSymbolAddress((void**)&psum,g_psum); cudaGetSymbolAddress((void**)&psq,g_psq);
  cudaGetSymbolAddress((void**)&tmp,g_tmp); cudaGetSymbolAddress((void**)&xm,g_xm);
  cudaGetSymbolAddress((void**)&gsum,g_gsum); cudaGetSymbolAddress((void**)&x4p,g_x4p);
  cudaGetSymbolAddress((void**)&xp,g_xp);   cudaGetSymbolAddress((void**)&hb,g_hb);
  cudaGetSymbolAddress((void**)&a1b,g_a1b); cudaGetSymbolAddress((void**)&a2b,g_a2b);
  cudaGetSymbolAddress((void**)&a1s,g_a1s); cudaGetSymbolAddress((void**)&a2s,g_a2s);
  cudaGetSymbolAddress((void**)&sigb,g_sigb); cudaGetSymbolAddress((void**)&attnb,g_attnb);
  cudaGetSymbolAddress((void**)&gaout,g_gaout);
  cudaGetSymbolAddress((void**)&mean,g_mean); cudaGetSymbolAddress((void**)&istd,g_istd);
  cudaGetSymbolAddress((void**)&idx1,g_idx1); cudaGetSymbolAddress((void**)&idx2,g_idx2);

  const int T=256;
  const int W_PA1=0, W_PA2=16384, W_LA=32768, W_FC1=69632, W_FC2=200704;

  static cudaStream_t s1=0,s2=0,s3=0;
  static cudaEvent_t evRoot=0,evSplit=0,ev1=0,ev2=0,ev3=0;
  if(!s1){
    cudaStreamCreateWithFlags(&s1,cudaStreamNonBlocking);
    cudaStreamCreateWithFlags(&s2,cudaStreamNonBlocking);
    cudaStreamCreateWithFlags(&s3,cudaStreamNonBlocking);
    cudaEventCreateWithFlags(&evRoot,cudaEventDisableTiming);
    cudaEventCreateWithFlags(&evSplit,cudaEventDisableTiming);
    cudaEventCreateWithFlags(&ev1,cudaEventDisableTiming);
    cudaEventCreateWithFlags(&ev2,cudaEventDisableTiming);
    cudaEventCreateWithFlags(&ev3,cudaEventDisableTiming);
  }

  cudaEventRecord(evRoot, 0);
  cudaStreamWaitEvent(s2, evRoot, 0);
  cudaStreamWaitEvent(s3, evRoot, 0);

  wsplit_all_k<<<1296,T>>>(pa_w1,pa_w2,la_w,mlp_w1,mlp_w2, wh, wl);
  xsplit_k<<<65536,T>>>(x, xh, xl);
  cudaEventRecord(evSplit, 0);
  cudaStreamWaitEvent(s1, evSplit, 0);

  tg2_k<128,true,false><<<dim3(2,1024),256>>>(wh+W_PA1, wl+W_PA1, 64,
      BSCopy{xh,xl}, EpSplitStore{bh,bl}, psum, psq, 256, nullptr, nullptr);
  bn_fin_k<<<256,T>>>(psum,psq,256, mean+0, istd+0);
  tg2_k<64,false,true><<<dim3(1,1024),256>>>(wh+W_PA2, wl+W_PA2, 256,
      BSCopy{bh,bl}, EpGateMulSplit{ph,pl,x}, nullptr,nullptr,0, mean+0, istd+0);

  tg2_k<64,true,false><<<dim3(1,1024),256,0,s1>>>(wh+W_LA, wl+W_LA, 576,
      BSIm2col{xh+(size_t)64*131072, xl+(size_t)64*131072}, EpStore{tmp,64,0},
      psum+262144, psq+262144, 64, nullptr, nullptr);
  bn_fin_k<<<64,T,0,s1>>>(psum+262144,psq+262144,64, mean+256, istd+256);
  la_apply_k<<<32768,T,0,s1>>>(tmp, ph, pl, mean+256, istd+256);

  blurpool_k<<<3872,T,0,s2>>>(x, xm);
  mra_strips_k<<<3872,T,0,s2>>>(mra_h1, mra_v1, mra_h2, mra_v2, xm, gsum);
  bn_stats_k<<<64,T,0,s2>>>(gsum,64,484, mean+320, istd+320);
  mra_apply_k<<<32768,T,0,s2>>>(x, gsum, ph, pl, mean+320, istd+320);

  pool2_k<<<8192,T,0,s3>>>(x, 256L*4096L, 192, 64, x4p, idx1, 32*64*1024);
  pool2_k<<<2048,T,0,s3>>>(x4p, 64L*1024L, 0, 32, xp, idx2, 32*64*256);
  ga_proj1_k<<<2048,T,0,s3>>>(xp, p1w, p1b, hb);
  ga_dw_k<<<2048,T,0,s3>>>(hb, c0w, c0b, spw, spb, a1b, a2b);
  ga_c1c2_k<<<2048,T,0,s3>>>(a1b, a2b, c1w, c1b, c2w, c2b, a1s, a2s);
  ga_aggsq_k<<<32,T,0,s3>>>(a1s, a2s, sqw, sqb, sigb);
  ga_attn_k<<<2048,T,0,s3>>>(a1s, a2s, sigb, cw, cb, attnb);
  ga_proj2_unpool_k<<<2048,T,0,s3>>>(hb, attnb, p2w, p2b, idx2, gaout);
  bn_stats_k<<<64,T,0,s3>>>(gaout,64,1024, mean+384, istd+384);
  ga_final_k<<<8192,T,0,s3>>>(gaout, idx1, ph, pl, mean+384, istd+384);

  cudaEventRecord(ev1,s1); cudaEventRecord(ev2,s2); cudaEventRecord(ev3,s3);
  cudaStreamWaitEvent(0, ev1, 0);
  cudaStreamWaitEvent(0, ev2, 0);
  cudaStreamWaitEvent(0, ev3, 0);

  tg2_k<128,true,false><<<dim3(4,1024),256>>>(wh+W_FC1, wl+W_FC1, 256,
      BSCopy{ph,pl}, EpSplitStore{bh,bl}, psum, psq, 512, nullptr, nullptr);
  bn_fin_k<<<512,T>>>(psum,psq,512, mean+448, istd+448);
  tg2_k<128,false,true><<<dim3(2,1024),256>>>(wh+W_FC2, wl+W_FC2, 512,
      BSCopy{bh,bl}, EpResidual{out,x}, nullptr,nullptr,0, mean+448, istd+448);
}

// round 15
// speedup vs baseline: 1.1737x; 1.0515x over previous
#include <cuda_runtime.h>
#include <cuda_bf16.h>
#include <math.h>

#define EPSF 1e-5f
typedef __nv_bfloat16 bf16;

// ---------------- scratch -----------------------------------------------------
__device__ bf16  g_ph[33554432];
__device__ bf16  g_pl[33554432];
__device__ bf16  g_bh[67108864];
__device__ bf16  g_bl[67108864];
__device__ bf16  g_xh[16777216];
__device__ bf16  g_xl[16777216];
__device__ bf16  g_wh[524288];
__device__ bf16  g_wl[524288];
__device__ float g_psum[524288];
__device__ float g_psq[524288];
__device__ float g_tmp[8388608];
__device__ float g_xm[32*64*484];
__device__ float g_gsum[32*64*484];
__device__ float g_x4p[32*64*1024];
__device__ unsigned char g_idx1[32*64*1024];
__device__ float g_xp[32*64*256];
__device__ unsigned char g_idx2[32*64*256];
__device__ float g_hb[32*64*256];
__device__ float g_a1b[32*64*256];
__device__ float g_a2b[32*64*256];
__device__ float g_a1s[32*32*256];
__device__ float g_a2s[32*32*256];
__device__ float g_sigb[32*2*256];
__device__ float g_attnb[32*64*256];
__device__ float g_gaout[32*64*1024];
__device__ float g_mean[1024];
__device__ float g_istd[1024];

__device__ __forceinline__ float sigmoidf_(float v){ return 1.0f/(1.0f+expf(-v)); }
__device__ __forceinline__ void split_store(float v, bf16* h, bf16* l, size_t i){
  bf16 hh=__float2bfloat16(v);
  h[i]=hh; l[i]=__float2bfloat16(v-__bfloat162float(hh));
}
__device__ __forceinline__ void cpa16(void* s, const void* g){
  unsigned sa=(unsigned)__cvta_generic_to_shared(s);
  asm volatile("cp.async.ca.shared.global [%0],[%1],16;"::"r"(sa),"l"(g));
}
__device__ __forceinline__ void ldmx4(unsigned* r, const bf16* p){
  unsigned a=(unsigned)__cvta_generic_to_shared(p);
  asm volatile("ldmatrix.sync.aligned.m8n8.x4.shared.b16 {%0,%1,%2,%3},[%4];"
   :"=r"(r[0]),"=r"(r[1]),"=r"(r[2]),"=r"(r[3]):"r"(a));
}
__device__ __forceinline__ void ldmx4t(unsigned* r, const bf16* p){
  unsigned a=(unsigned)__cvta_generic_to_shared(p);
  asm volatile("ldmatrix.sync.aligned.m8n8.x4.trans.shared.b16 {%0,%1,%2,%3},[%4];"
   :"=r"(r[0]),"=r"(r[1]),"=r"(r[2]),"=r"(r[3]):"r"(a));
}
__device__ __forceinline__ void mma16816(float* c,const unsigned* a,const unsigned* b){
  asm volatile("mma.sync.aligned.m16n8k16.row.col.f32.bf16.bf16.f32 "
    "{%0,%1,%2,%3},{%4,%5,%6,%7},{%8,%9},{%0,%1,%2,%3};"
    :"+f"(c[0]),"+f"(c[1]),"+f"(c[2]),"+f"(c[3])
    :"r"(a[0]),"r"(a[1]),"r"(a[2]),"r"(a[3]),"r"(b[0]),"r"(b[1]));
}

// ---------------- B stagers (BK=16) --------------------------------------------
#define PBP 136
struct BSCopy {
  const bf16 *bh, *bl;
  __device__ __forceinline__ void stage(bf16* Bh, bf16* Bl, int k0, int n0, int tid) const {
    int k=tid>>4, nc=(tid&15)*8;
    cpa16(&Bh[k*PBP+nc], bh+(size_t)(k0+k)*131072+n0+nc);
    cpa16(&Bl[k*PBP+nc], bl+(size_t)(k0+k)*131072+n0+nc);
  }
};
struct BSXSplit {             // fp32 x channels (c0..): split-on-stage (plain STS)
  const float* x; int c0;
  __device__ __forceinline__ void stage(bf16* Bh, bf16* Bl, int k0, int n0, int tid) const {
    int k=tid>>4, nc=(tid&15)*8;
    int na=n0+nc; int b=na>>12, p=na&4095;
    const float* src=x+((size_t)(b*256+c0+k0+k)<<12)+p;
    float4 v0=*(const float4*)src, v1=*(const float4*)(src+4);
    float vv[8]={v0.x,v0.y,v0.z,v0.w,v1.x,v1.y,v1.z,v1.w};
#pragma unroll
    for(int e=0;e<8;e++){
      bf16 hh=__float2bfloat16(vv[e]);
      Bh[k*PBP+nc+e]=hh;
      Bl[k*PBP+nc+e]=__float2bfloat16(vv[e]-__bfloat162float(hh));
    }
  }
};
struct BSIm2col {
  const bf16 *xh, *xl;
  __device__ __forceinline__ void stage(bf16* Bh, bf16* Bl, int k0, int n0, int tid) const {
#pragma unroll
    for(int it=0;it<8;it++){
      int id=it*256+tid; int k=id>>7, n=id&127;
      int kk=k0+k;
      int ic=kk/9; int t=kk-ic*9; int dy=t/3-1, dx=t%3-1;
      int na=n0+n; int p=na&4095;
      int h=(p>>6)+dy, w=(p&63)+dx;
      bf16 vh, vl;
      if((unsigned)h>63u||(unsigned)w>63u){ vh=__float2bfloat16(0.f); vl=vh; }
      else{
        size_t gi=(size_t)ic*131072+(size_t)(na&~4095)+h*64+w;
        vh=xh[gi]; vl=xl[gi];
      }
      Bh[k*PBP+n]=vh; Bl[k*PBP+n]=vl;
    }
  }
};

// ---------------- epilogues ---------------------------------------------------
struct EpStore {
  float* o; int MC; int oc0;
  __device__ __forceinline__ void operator()(int m,int n,float a) const {
    int b=n>>12,p=n&4095;
    o[((size_t)(b*MC+oc0+m)<<12)+p]=a;
  }
};
struct EpSplitStore {
  bf16 *oh,*ol;
  __device__ __forceinline__ void operator()(int m,int n,float a) const {
    split_store(a, oh, ol, (size_t)m*131072+n);
  }
};
struct EpGateMulSplit {
  bf16 *ph,*pl; const float* x;
  __device__ __forceinline__ void operator()(int m,int n,float a) const {
    int b=n>>12,p=n&4095;
    float v=x[((size_t)(b*256+m)<<12)+p]*sigmoidf_(a);
    split_store(v, ph, pl, (size_t)m*131072+n);
  }
};
struct EpResidual {
  float* o; const float* x;
  __device__ __forceinline__ void operator()(int m,int n,float a) const {
    int b=n>>12,p=n&4095;
    size_t i=((size_t)(b*256+m)<<12)+p;
    o[i]=x[i]+a;
  }
};

// ------- GEMM: triple-buffered, ONE barrier per k-tile, BK=16, 3-pass MMA -------
#define PA_ 24
#define SMEM128 (6*128*PA_*2 + 6*16*PBP*2)
#define SMEM64  (6*64*PA_*2  + 6*16*PBP*2)
template<int BM,bool STATS,bool BNORMOWN,class BS,class EP>
__global__ __launch_bounds__(256,2)
void tg2_k(const bf16* __restrict__ wh, const bf16* __restrict__ wl,
           int K, BS bs, EP ep,
           float* __restrict__ psum, float* __restrict__ psq, int C,
           const float* __restrict__ mean, const float* __restrict__ istd){
  constexpr int WTM=BM/2, MI=WTM/16;
  extern __shared__ __align__(16) bf16 SM[];
  bf16* Ah=SM;                 // [3][BM*PA_]
  bf16* Al=SM+3*BM*PA_;
  bf16* Bhs=SM+6*BM*PA_;       // [3][16*PBP]
  bf16* Bls=SM+6*BM*PA_+3*16*PBP;
  __shared__ float sS4[4*BM], sQ4[4*BM];
  const int tid=threadIdx.x;
  const int warp=tid>>5, lane=tid&31;
  const int wm=warp>>2, wn=warp&3;
  const int m0=blockIdx.x*BM, n0=blockIdx.y*128;
  float c[MI][4][4];
#pragma unroll
  for(int i=0;i<MI;i++)
#pragma unroll
    for(int j=0;j<4;j++)
#pragma unroll
      for(int q=0;q<4;q++) c[i][j][q]=0.f;
  auto stageA=[&](int buf,int k0){
    for(int id=tid; id<BM*2; id+=256){
      int m=id>>1, kc=(id&1)*8;
      cpa16(&Ah[buf*BM*PA_+m*PA_+kc], wh+(size_t)(m0+m)*K+k0+kc);
      cpa16(&Al[buf*BM*PA_+m*PA_+kc], wl+(size_t)(m0+m)*K+k0+kc);
    }
  };
  const int KT=K/16;
  stageA(0,0); bs.stage(Bhs,Bls,0,n0,tid);
  asm volatile("cp.async.commit_group;");
  if(KT>1){
    stageA(1,16); bs.stage(Bhs+16*PBP,Bls+16*PBP,16,n0,tid);
    asm volatile("cp.async.commit_group;");
  }
  for(int kt=0;kt<KT;kt++){
    const int buf=kt%3;
    bf16* bh_=Bhs+buf*16*PBP;
    bf16* bl_=Bls+buf*16*PBP;
    if(kt+1<KT) asm volatile("cp.async.wait_group 1;");
    else        asm volatile("cp.async.wait_group 0;");
    if(BNORMOWN){
      int k=tid>>4, nc=(tid&15)*8;
      float mm=__ldg(&mean[kt*16+k]), is=__ldg(&istd[kt*16+k]);
      bf16* bph=&bh_[k*PBP+nc];
      bf16* bpl=&bl_[k*PBP+nc];
#pragma unroll
      for(int e=0;e<8;e++){
        float v=__bfloat162float(bph[e])+__bfloat162float(bpl[e]);
        v=(v-mm)*is; v=v>0.f?v:0.f;
        bf16 hh=__float2bfloat16(v);
        bph[e]=hh; bpl[e]=__float2bfloat16(v-__bfloat162float(hh));
      }
    }
    __syncthreads();                 // single barrier per k-tile
    if(kt+2<KT){
      int nb=(kt+2)%3;
      stageA(nb,(kt+2)*16);
      bs.stage(Bhs+nb*16*PBP,Bls+nb*16*PBP,(kt+2)*16,n0,tid);
      asm volatile("cp.async.commit_group;");
    }
    // ---- compute buf: 3 passes of independent MMAs ----
    const int arow=lane&15, acol=(lane>>4)<<3;
    const bf16* ah_=Ah+buf*BM*PA_;
    const bf16* al_=Al+buf*BM*PA_;
    unsigned a4[MI][4];
    unsigned b4h[2][4], b4l[2][4];
#pragma unroll
    for(int np=0;np<2;np++){
      int rb=(lane&15)*PBP+wn*32+np*16+((lane>>4)<<3);
      ldmx4t(b4h[np], &bh_[rb]);
      ldmx4t(b4l[np], &bl_[rb]);
    }
#pragma unroll
    for(int mi=0;mi<MI;mi++)
      ldmx4(a4[mi], &ah_[(wm*WTM+mi*16+arow)*PA_+acol]);
#pragma unroll
    for(int np=0;np<2;np++)
#pragma unroll
      for(int t2=0;t2<2;t2++)
#pragma unroll
        for(int mi=0;mi<MI;mi++)
          mma16816(c[mi][np*2+t2], a4[mi], &b4h[np][t2*2]);
#pragma unroll
    for(int np=0;np<2;np++)
#pragma unroll
      for(int t2=0;t2<2;t2++)
#pragma unroll
        for(int mi=0;mi<MI;mi++)
          mma16816(c[mi][np*2+t2], a4[mi], &b4l[np][t2*2]);
#pragma unroll
    for(int mi=0;mi<MI;mi++)
      ldmx4(a4[mi], &al_[(wm*WTM+mi*16+arow)*PA_+acol]);
#pragma unroll
    for(int np=0;np<2;np++)
#pragma unroll
      for(int t2=0;t2<2;t2++)
#pragma unroll
        for(int mi=0;mi<MI;mi++)
          mma16816(c[mi][np*2+t2], a4[mi], &b4h[np][t2*2]);
  }
  __syncthreads();
  if(STATS){
#pragma unroll
    for(int mi=0;mi<MI;mi++){
      float s1=0.f,q1=0.f,s2=0.f,q2=0.f;
#pragma unroll
      for(int ni=0;ni<4;ni++){
        s1+=c[mi][ni][0]+c[mi][ni][1];
        q1+=c[mi][ni][0]*c[mi][ni][0]+c[mi][ni][1]*c[mi][ni][1];
        s2+=c[mi][ni][2]+c[mi][ni][3];
        q2+=c[mi][ni][2]*c[mi][ni][2]+c[mi][ni][3]*c[mi][ni][3];
      }
#pragma unroll
      for(int off=1;off<4;off<<=1){
        s1+=__shfl_xor_sync(0xffffffffu,s1,off);
        q1+=__shfl_xor_sync(0xffffffffu,q1,off);
        s2+=__shfl_xor_sync(0xffffffffu,s2,off);
        q2+=__shfl_xor_sync(0xffffffffu,q2,off);
      }
      if((lane&3)==0){
        int mr=wm*WTM+mi*16+(lane>>2);
        sS4[wn*BM+mr]=s1; sQ4[wn*BM+mr]=q1;
        sS4[wn*BM+mr+8]=s2; sQ4[wn*BM+mr+8]=q2;
      }
    }
    __syncthreads();
    for(int i=tid;i<BM;i+=256){
      float s=sS4[i]+sS4[BM+i]+sS4[2*BM+i]+sS4[3*BM+i];
      float q=sQ4[i]+sQ4[BM+i]+sQ4[2*BM+i]+sQ4[3*BM+i];
      psum[(size_t)blockIdx.y*C+m0+i]=s;
      psq [(size_t)blockIdx.y*C+m0+i]=q;
    }
  }
  const int r=lane>>2, q=lane&3;
#pragma unroll
  for(int mi=0;mi<MI;mi++)
#pragma unroll
    for(int ni=0;ni<4;ni++){
      int m=m0+wm*WTM+mi*16+r;
      int n=n0+wn*32+ni*8+2*q;
      ep(m,   n,   c[mi][ni][0]);
      ep(m,   n+1, c[mi][ni][1]);
      ep(m+8, n,   c[mi][ni][2]);
      ep(m+8, n+1, c[mi][ni][3]);
    }
}

// ---------------- stats finalize -----------------------------------------------
__global__ void bn_fin_k(const float* __restrict__ psum, const float* __restrict__ psq,
                         int C, float* __restrict__ mean, float* __restrict__ istd){
  int c=blockIdx.x;
  float s=0.f,q=0.f;
  for(int i=threadIdx.x;i<1024;i+=256){ s+=psum[(size_t)i*C+c]; q+=psq[(size_t)i*C+c]; }
  __shared__ float sh[256], sh2[256];
  sh[threadIdx.x]=s; sh2[threadIdx.x]=q; __syncthreads();
  for(int o=128;o>0;o>>=1){
    if(threadIdx.x<o){ sh[threadIdx.x]+=sh[threadIdx.x+o]; sh2[threadIdx.x]+=sh2[threadIdx.x+o]; }
    __syncthreads();
  }
  if(threadIdx.x==0){
    float m=sh[0]*(1.f/131072.f);
    float v=sh2[0]*(1.f/131072.f)-m*m;
    mean[c]=m; istd[c]=rsqrtf(v+EPSF);
  }
}

// ---------------- split kernels ---------------------------------------------------
__global__ void wsplit_all_k(const float* __restrict__ w1,const float* __restrict__ w2,
                             const float* __restrict__ w3,const float* __restrict__ w4,
                             const float* __restrict__ w5,
                             bf16* __restrict__ h, bf16* __restrict__ l){
  int i=blockIdx.x*blockDim.x+threadIdx.x;
  if(i>=331776) return;
  const float* src; int off;
  if(i<16384){src=w1;off=0;}
  else if(i<32768){src=w2;off=16384;}
  else if(i<69632){src=w3;off=32768;}
  else if(i<200704){src=w4;off=69632;}
  else {src=w5;off=200704;}
  split_store(src[i-off], h, l, i);
}
__global__ void xsplit_k(const float* __restrict__ x, bf16* __restrict__ xh,
                         bf16* __restrict__ xl){
  int i=blockIdx.x*blockDim.x+threadIdx.x;
  if(i>=32*64*4096) return;
  int p=i&4095; int bc=i>>12; int ch=bc&63; int b=bc>>6;
  float v=x[((size_t)(b*256+64+ch)<<12)+p];
  split_store(v, xh, xl, (size_t)ch*131072+b*4096+p);
}
__global__ void bn_stats_k(const float* __restrict__ d, int C, int S,
                           float* __restrict__ mean, float* __restrict__ istd){
  int c=blockIdx.x;
  double s=0.0,s2=0.0;
  for(int b=0;b<32;b++){
    const float* P=d+(size_t)(b*C+c)*S;
    for(int off=threadIdx.x;off<S;off+=256){
      float v=P[off]; s+=(double)v; s2+=(double)v*(double)v;
    }
  }
  __shared__ double sh[256], sh2[256];
  sh[threadIdx.x]=s; sh2[threadIdx.x]=s2; __syncthreads();
  for(int o=128;o>0;o>>=1){
    if(threadIdx.x<o){ sh[threadIdx.x]+=sh[threadIdx.x+o]; sh2[threadIdx.x]+=sh2[threadIdx.x+o]; }
    __syncthreads();
  }
  if(threadIdx.x==0){
    double N=32.0*(double)S;
    double m=sh[0]/N, v=sh2[0]/N-m*m;
    mean[c]=(float)m; istd[c]=rsqrtf((float)v+EPSF);
  }
}
__global__ void la_apply_k(const float* __restrict__ t, bf16* __restrict__ ph,
                           bf16* __restrict__ pl,
                           const float* __restrict__ mean, const float* __restrict__ istd){
  int i=blockIdx.x*blockDim.x+threadIdx.x;
  if(i>=32*64*4096) return;
  int p=i&4095; int bc=i>>12; int c=bc&63; int b=bc>>6;
  float v=(t[i]-mean[c])*istd[c];
  v=v>0.f?v:0.f;
  split_store(v, ph, pl, (size_t)(64+c)*131072+b*4096+p);
}
__global__ void blurpool_k(const float* __restrict__ x, float* __restrict__ xm){
  int i=blockIdx.x*blockDim.x+threadIdx.x;
  if(i>=32*64*484) return;
  int s=i%484; int bc=i/484; int c=bc&63; int b=bc>>6;
  const float* X=x+(((size_t)(b*256+128+c))<<12);
  int oh=s/22, ow=s%22;
  const float f0[4]={1.f,3.f,3.f,1.f};
  float acc=0.f;
  for(int iy=0;iy<4;iy++){
    int u=3*oh+iy-1; u=u<0?-u:u; u=u>63?126-u:u;
    float fy=f0[iy];
    for(int ix=0;ix<4;ix++){
      int v=3*ow+ix-1; v=v<0?-v:v; v=v>63?126-v:v;
      float m=-3.4e38f;
      for(int dy=-1;dy<=1;dy++){
        int yy=u+dy; if((unsigned)yy>63u) continue;
        for(int dx=-1;dx<=1;dx++){
          int xx=v+dx; if((unsigned)xx>63u) continue;
          float vv=X[yy*64+xx]; m=vv>m?vv:m;
        }
      }
      acc+=fy*f0[ix]*m;
    }
  }
  xm[i]=acc*(1.f/64.f);
}
__global__ void mra_strips_k(const float* __restrict__ wh1, const float* __restrict__ wv1,
                             const float* __restrict__ wh2, const float* __restrict__ wv2,
                             const float* __restrict__ xm, float* __restrict__ gsum){
  int i=blockIdx.x*blockDim.x+threadIdx.x;
  if(i>=32*64*484) return;
  int s=i%484; int bc=i/484; int c=bc&63;
  int r=s/22, cc=s%22;
  const float* X=xm+(size_t)bc*484;
  const float* W1=wh1+c*33; const float* V1=wv1+c*33;
  const float* W2=wh2+c*33; const float* V2=wv2+c*33;
  float acc=0.f;
  for(int ky=0;ky<11;ky++){
    int y=r+ky-5; if((unsigned)y>=22u) continue;
    for(int kx=0;kx<3;kx++){
      int x2=cc+kx-1; if((unsigned)x2>=22u) continue;
      acc+=W1[ky*3+kx]*X[y*22+x2];
    }
  }
  for(int ky=0;ky<3;ky++){
    int y=r+ky-1; if((unsigned)y>=22u) continue;
    for(int kx=0;kx<11;kx++){
      int x2=cc+kx-5; if((unsigned)x2>=22u) continue;
      acc+=V1[ky*11+kx]*X[y*22+x2];
    }
  }
  {
    int i2=r*44+cc; int R=i2/43, C=i2-43*R;
    for(int ky=0;ky<11;ky++){
      int RR=R+ky-5; if((unsigned)RR>=22u) continue;
      for(int kx=0;kx<3;kx++){
        int CC=C+kx-1; if((unsigned)CC>=43u) continue;
        int j=RR*43+CC; int q=j/44, m=j-44*q;
        if(m<22) acc+=W2[ky*3+kx]*X[q*22+m];
      }
    }
  }
  {
    int j=cc*44+r; int b2=j/43, a2=j-43*b2;
    for(int ky=0;ky<3;ky++){
      int RR=a2+ky-1; if((unsigned)RR>=43u) continue;
      for(int kx=0;kx<11;kx++){
        int CC=b2+kx-5; if((unsigned)CC>=22u) continue;
        int j2=CC*43+RR; int q=j2/44, m=j2-44*q;
        if(m<22) acc+=V2[ky*11+kx]*X[m*22+q];
      }
    }
  }
  gsum[i]=acc;
}
__global__ void mra_apply_k(const float* __restrict__ x, const float* __restrict__ gsum,
                            bf16* __restrict__ ph, bf16* __restrict__ pl,
                            const float* __restrict__ mean, const float* __restrict__ istd){
  int i=blockIdx.x*blockDim.x+threadIdx.x;
  if(i>=32*64*4096) return;
  int p=i&4095, bc=i>>12, c=bc&63, b=bc>>6;
  int h=p>>6, w=p&63;
  int ri=(h*22)>>6, ci=(w*22)>>6;
  float g=gsum[(size_t)bc*484+ri*22+ci];
  g=sigmoidf_((g-mean[c])*istd[c]);
  float v=x[((size_t)(b*256+128+c)<<12)+p]*g;
  split_store(v, ph, pl, (size_t)(128+c)*131072+b*4096+p);
}
__global__ void pool2_k(const float* __restrict__ in, long bstride, int c0, int inW,
                        float* __restrict__ out, unsigned char* __restrict__ idx, int total){
  int i=blockIdx.x*blockDim.x+threadIdx.x;
  if(i>=total) return;
  int outW=inW>>1; int os=outW*outW;
  int s=i%os; int bc=i/os; int b=bc>>6, c=bc&63;
  int oh=s/outW, ow=s-oh*outW;
  const float* P=in+(size_t)b*bstride+(size_t)(c0+c)*inW*inW;
  float v0=P[(2*oh)*inW+2*ow],   v1=P[(2*oh)*inW+2*ow+1];
  float v2=P[(2*oh+1)*inW+2*ow], v3=P[(2*oh+1)*inW+2*ow+1];
  float best=v0; int bi=0;
  if(v1>best){best=v1;bi=1;}
  if(v2>best){best=v2;bi=2;}
  if(v3>best){best=v3;bi=3;}
  out[i]=best; idx[i]=(unsigned char)bi;
}
__global__ void ga_proj1_k(const float* __restrict__ xp, const float* __restrict__ w,
                           const float* __restrict__ bias, float* __restrict__ hb){
  int i=blockIdx.x*blockDim.x+threadIdx.x;
  if(i>=32*64*256) return;
  int s=i&255; int boc=i>>8; int oc=boc&63; int b=boc>>6;
  const float* X=xp+(size_t)b*64*256;
  float acc=bias[oc];
  for(int ic=0;ic<64;ic++) acc+=w[oc*64+ic]*X[ic*256+s];
  hb[i]=acc>0.f?acc:0.f;
}
__global__ void ga_dw_k(const float* __restrict__ hb,
                        const float* __restrict__ c0w, const float* __restrict__ c0b,
                        const float* __restrict__ spw, const float* __restrict__ spb,
                        float* __restrict__ a1, float* __restrict__ a2){
  int bc=blockIdx.x; int c=bc&63;
  int s=threadIdx.x;
  int y=s>>4, x=s&15;
  __shared__ float A1[256];
  const float* H=hb+(size_t)bc*256;
  float acc=c0b[c];
  for(int ky=0;ky<5;ky++){
    int yy=y+ky-2; if((unsigned)yy>15u) continue;
    for(int kx=0;kx<5;kx++){
      int xx=x+kx-2; if((unsigned)xx>15u) continue;
      acc+=c0w[c*25+ky*5+kx]*H[yy*16+xx];
    }
  }
  A1[s]=acc; a1[(size_t)bc*256+s]=acc;
  __syncthreads();
  float acc2=spb[c];
  for(int ky=0;ky<7;ky++){
    int yy=y+3*ky-9; if((unsigned)yy>15u) continue;
    for(int kx=0;kx<7;kx++){
      int xx=x+3*kx-9; if((unsigned)xx>15u) continue;
      acc2+=spw[c*49+ky*7+kx]*A1[yy*16+xx];
    }
  }
  a2[(size_t)bc*256+s]=acc2;
}
__global__ void ga_c1c2_k(const float* __restrict__ a1, const float* __restrict__ a2,
                          const float* __restrict__ c1w, const float* __restrict__ c1b,
                          const float* __restrict__ c2w, const float* __restrict__ c2b,
                          float* __restrict__ a1s, float* __restrict__ a2s){
  int i=blockIdx.x*blockDim.x+threadIdx.x;
  if(i>=2*32*32*256) return;
  int which=i/(32*32*256); int rr=i-which*(32*32*256);
  int s=rr&255; int bj=rr>>8; int j=bj&31; int b=bj>>5;
  const float* src=which?a2:a1;
  const float* W=which?c2w:c1w;
  const float* Bb=which?c2b:c1b;
  const float* S=src+(size_t)b*64*256;
  float acc=Bb[j];
  for(int ic=0;ic<64;ic++) acc+=W[j*64+ic]*S[ic*256+s];
  (which?a2s:a1s)[(size_t)(b*32+j)*256+s]=acc;
}
__global__ void ga_aggsq_k(const float* __restrict__ a1s, const float* __restrict__ a2s,
                           const float* __restrict__ sqw, const float* __restrict__ sqb,
                           float* __restrict__ sg){
  int b=blockIdx.x; int s=threadIdx.x;
  __shared__ float AG[2][256];
  const float* A1=a1s+(size_t)b*32*256;
  const float* A2=a2s+(size_t)b*32*256;
  float sum=0.f, mx=-3.4e38f;
  for(int j=0;j<32;j++){
    float v1=A1[j*256+s]; sum+=v1; mx=v1>mx?v1:mx;
    float v2=A2[j*256+s]; sum+=v2; mx=v2>mx?v2:mx;
  }
  AG[0][s]=sum*(1.f/64.f); AG[1][s]=mx;
  __syncthreads();
  int y=s>>4, x=s&15;
  for(int o=0;o<2;o++){
    float acc=sqb[o];
    for(int ic=0;ic<2;ic++){
      const float* W=sqw+((o*2+ic)*49);
      for(int ky=0;ky<7;ky++){
        int yy=y+ky-3; if((unsigned)yy>15u) continue;
        for(int kx=0;kx<7;kx++){
          int xx=x+kx-3; if((unsigned)xx>15u) continue;
          acc+=W[ky*7+kx]*AG[ic][yy*16+xx];
        }
      }
    }
    sg[(size_t)(b*2+o)*256+s]=sigmoidf_(acc);
  }
}
__global__ void ga_attn_k(const float* __restrict__ a1s, const float* __restrict__ a2s,
                          const float* __restrict__ sg, const float* __restrict__ cw,
                          const float* __restrict__ cb, float* __restrict__ attn){
  int i=blockIdx.x*blockDim.x+threadIdx.x;
  if(i>=32*64*256) return;
  int s=i&255; int boc=i>>8; int oc=boc&63; int b=boc>>6;
  float s0=sg[(size_t)(b*2+0)*256+s];
  float s1=sg[(size_t)(b*2+1)*256+s];
  const float* A1=a1s+(size_t)b*32*256;
  const float* A2=a2s+(size_t)b*32*256;
  float acc=cb[oc];
  for(int j=0;j<32;j++)
    acc+=cw[oc*32+j]*(A1[j*256+s]*s0+A2[j*256+s]*s1);
  attn[i]=acc;
}
__global__ void ga_proj2_unpool_k(const float* __restrict__ hb, const float* __restrict__ attn,
                                  const float* __restrict__ w, const float* __restrict__ bias,
                                  const unsigned char* __restrict__ idx2, float* __restrict__ out){
  int i=blockIdx.x*blockDim.x+threadIdx.x;
  if(i>=32*64*256) return;
  int s=i&255; int boc=i>>8; int oc=boc&63; int b=boc>>6;
  const float* H=hb+(size_t)b*64*256;
  const float* A=attn+(size_t)b*64*256;
  float acc=bias[oc];
  for(int ic=0;ic<64;ic++) acc+=w[oc*64+ic]*H[ic*256+s]*A[ic*256+s];
  int id=idx2[i];
  int y=s>>4, x=s&15;
  float* O=out+(size_t)boc*1024;
  for(int dy=0;dy<2;dy++)
    for(int dx=0;dx<2;dx++)
      O[(2*y+dy)*32+2*x+dx]=(dy*2+dx==id)?acc:0.f;
}
__global__ void ga_final_k(const float* __restrict__ gaout, const unsigned char* __restrict__ idx1,
                           bf16* __restrict__ ph, bf16* __restrict__ pl,
                           const float* __restrict__ mean, const float* __restrict__ istd){
  int i=blockIdx.x*blockDim.x+threadIdx.x;
  if(i>=32*64*1024) return;
  int s=i&1023; int bc=i>>10; int c=bc&63; int b=bc>>6;
  float v=(gaout[i]-mean[c])*istd[c];
  int id=idx1[i];
  int y=s>>5, x=s&31;
  size_t base=(size_t)(192+c)*131072+b*4096;
  for(int dy=0;dy<2;dy++)
    for(int dx=0;dx<2;dx++){
      float o=(dy*2+dx==id)?v:0.f;
      split_store(o, ph, pl, base+(2*y+dy)*64+2*x+dx);
    }
}

// ---------------- launch ----------------------------------------------------------
extern "C" void kernel_launch(void* const* d_in, const int* in_sizes, int n_in,
                              void* d_out, int out_size) {
  const float* x      =(const float*)d_in[0];
  const float* pa_w1  =(const float*)d_in[1];
  const float* pa_w2  =(const float*)d_in[2];
  const float* la_w   =(const float*)d_in[3];
  const float* mra_h1 =(const float*)d_in[4];
  const float* mra_v1 =(const float*)d_in[5];
  const float* mra_h2 =(const float*)d_in[6];
  const float* mra_v2 =(const float*)d_in[7];
  const float* p1w=(const float*)d_in[8];  const float* p1b=(const float*)d_in[9];
  const float* c0w=(const float*)d_in[10]; const float* c0b=(const float*)d_in[11];
  const float* spw=(const float*)d_in[12]; const float* spb=(const float*)d_in[13];
  const float* c1w=(const float*)d_in[14]; const float* c1b=(const float*)d_in[15];
  const float* c2w=(const float*)d_in[16]; const float* c2b=(const float*)d_in[17];
  const float* cw =(const float*)d_in[18]; const float* cb =(const float*)d_in[19];
  const float* sqw=(const float*)d_in[20]; const float* sqb=(const float*)d_in[21];
  const float* p2w=(const float*)d_in[22]; const float* p2b=(const float*)d_in[23];
  const float* mlp_w1=(const float*)d_in[24];
  const float* mlp_w2=(const float*)d_in[25];
  float* out=(float*)d_out;

  float *tmp,*xm,*gsum,*x4p,*xp,*hb,*a1b,*a2b,*a1s,*a2s,*sigb,*attnb,*gaout,*mean,*istd,*psum,*psq;
  bf16 *ph,*pl,*bh,*bl,*xh,*xl,*wh,*wl;
  unsigned char *idx1,*idx2;
  cudaGetSymbolAddress((void**)&ph,g_ph);   cudaGetSymbolAddress((void**)&pl,g_pl);
  cudaGetSymbolAddress((void**)&bh,g_bh);   cudaGetSymbolAddress((void**)&bl,g_bl);
  cudaGetSymbolAddress((void**)&xh,g_xh);   cudaGetSymbolAddress((void**)&xl,g_xl);
  cudaGetSymbolAddress((void**)&wh,g_wh);   cudaGetSymbolAddress((void**)&wl,g_wl);
  cudaGetSymbolAddress((void**)&psum,g_psum); cudaGetSymbolAddress((void**)&psq,g_psq);
  cudaGetSymbolAddress((void**)&tmp,g_tmp); cudaGetSymbolAddress((void**)&xm,g_xm);
  cudaGetSymbolAddress((void**)&gsum,g_gsum); cudaGetSymbolAddress((void**)&x4p,g_x4p);
  cudaGetSymbolAddress((void**)&xp,g_xp);   cudaGetSymbolAddress((void**)&hb,g_hb);
  cudaGetSymbolAddress((void**)&a1b,g_a1b); cudaGetSymbolAddress((void**)&a2b,g_a2b);
  cudaGetSymbolAddress((void**)&a1s,g_a1s); cudaGetSymbolAddress((void**)&a2s,g_a2s);
  cudaGetSymbolAddress((void**)&sigb,g_sigb); cudaGetSymbolAddress((void**)&attnb,g_attnb);
  cudaGetSymbolAddress((void**)&gaout,g_gaout);
  cudaGetSymbolAddress((void**)&mean,g_mean); cudaGetSymbolAddress((void**)&istd,g_istd);
  cudaGetSymbolAddress((void**)&idx1,g_idx1); cudaGetSymbolAddress((void**)&idx2,g_idx2);

  const int T=256;
  const int W_PA1=0, W_PA2=16384, W_LA=32768, W_FC1=69632, W_FC2=200704;

  static cudaStream_t s1=0,s2=0,s3=0;
  static cudaEvent_t evRoot=0,evW=0,ev1=0,ev2=0,ev3=0;
  if(!s1){
    cudaStreamCreateWithFlags(&s1,cudaStreamNonBlocking);
    cudaStreamCreateWithFlags(&s2,cudaStreamNonBlocking);
    cudaStreamCreateWithFlags(&s3,cudaStreamNonBlocking);
    cudaEventCreateWithFlags(&evRoot,cudaEventDisableTiming);
    cudaEventCreateWithFlags(&evW,cudaEventDisableTiming);
    cudaEventCreateWithFlags(&ev1,cudaEventDisableTiming);
    cudaEventCreateWithFlags(&ev2,cudaEventDisableTiming);
    cudaEventCreateWithFlags(&ev3,cudaEventDisableTiming);
    cudaFuncSetAttribute((const void*)tg2_k<128,true,false,BSXSplit,EpSplitStore>,
                         cudaFuncAttributeMaxDynamicSharedMemorySize, SMEM128);
    cudaFuncSetAttribute((const void*)tg2_k<64,false,true,BSCopy,EpGateMulSplit>,
                         cudaFuncAttributeMaxDynamicSharedMemorySize, SMEM64);
    cudaFuncSetAttribute((const void*)tg2_k<64,true,false,BSIm2col,EpStore>,
                         cudaFuncAttributeMaxDynamicSharedMemorySize, SMEM64);
    cudaFuncSetAttribute((const void*)tg2_k<128,true,false,BSCopy,EpSplitStore>,
                         cudaFuncAttributeMaxDynamicSharedMemorySize, SMEM128);
    cudaFuncSetAttribute((const void*)tg2_k<128,false,true,BSCopy,EpResidual>,
                         cudaFuncAttributeMaxDynamicSharedMemorySize, SMEM128);
  }

  cudaEventRecord(evRoot, 0);
  cudaStreamWaitEvent(s2, evRoot, 0);
  cudaStreamWaitEvent(s3, evRoot, 0);

  // ---- main: weight split, then PA chain (PA1 reads fp32 x directly) ----
  wsplit_all_k<<<1296,T>>>(pa_w1,pa_w2,la_w,mlp_w1,mlp_w2, wh, wl);
  cudaEventRecord(evW, 0);
  cudaStreamWaitEvent(s1, evW, 0);

  tg2_k<128,true,false><<<dim3(2,1024),256,SMEM128>>>(wh+W_PA1, wl+W_PA1, 64,
      BSXSplit{x,0}, EpSplitStore{bh,bl}, psum, psq, 256, nullptr, nullptr);
  bn_fin_k<<<256,T>>>(psum,psq,256, mean+0, istd+0);
  tg2_k<64,false,true><<<dim3(1,1024),256,SMEM64>>>(wh+W_PA2, wl+W_PA2, 256,
      BSCopy{bh,bl}, EpGateMulSplit{ph,pl,x}, nullptr,nullptr,0, mean+0, istd+0);

  // ---- s1: xsplit (ch64..127 only, for LA im2col) then LA chain ----
  xsplit_k<<<32768,T,0,s1>>>(x, xh, xl);
  tg2_k<64,true,false><<<dim3(1,1024),256,SMEM64,s1>>>(wh+W_LA, wl+W_LA, 576,
      BSIm2col{xh, xl}, EpStore{tmp,64,0},
      psum+262144, psq+262144, 64, nullptr, nullptr);
  bn_fin_k<<<64,T,0,s1>>>(psum+262144,psq+262144,64, mean+256, istd+256);
  la_apply_k<<<32768,T,0,s1>>>(tmp, ph, pl, mean+256, istd+256);

  blurpool_k<<<3872,T,0,s2>>>(x, xm);
  mra_strips_k<<<3872,T,0,s2>>>(mra_h1, mra_v1, mra_h2, mra_v2, xm, gsum);
  bn_stats_k<<<64,T,0,s2>>>(gsum,64,484, mean+320, istd+320);
  mra_apply_k<<<32768,T,0,s2>>>(x, gsum, ph, pl, mean+320, istd+320);

  pool2_k<<<8192,T,0,s3>>>(x, 256L*4096L, 192, 64, x4p, idx1, 32*64*1024);
  pool2_k<<<2048,T,0,s3>>>(x4p, 64L*1024L, 0, 32, xp, idx2, 32*64*256);
  ga_proj1_k<<<2048,T,0,s3>>>(xp, p1w, p1b, hb);
  ga_dw_k<<<2048,T,0,s3>>>(hb, c0w, c0b, spw, spb, a1b, a2b);
  ga_c1c2_k<<<2048,T,0,s3>>>(a1b, a2b, c1w, c1b, c2w, c2b, a1s, a2s);
  ga_aggsq_k<<<32,T,0,s3>>>(a1s, a2s, sqw, sqb, sigb);
  ga_attn_k<<<2048,T,0,s3>>>(a1s, a2s, sigb, cw, cb, attnb);
  ga_proj2_unpool_k<<<2048,T,0,s3>>>(hb, attnb, p2w, p2b, idx2, gaout);
  bn_stats_k<<<64,T,0,s3>>>(gaout,64,1024, mean+384, istd+384);
  ga_final_k<<<8192,T,0,s3>>>(gaout, idx1, ph, pl, mean+384, istd+384);

  cudaEventRecord(ev1,s1); cudaEventRecord(ev2,s2); cudaEventRecord(ev3,s3);
  cudaStreamWaitEvent(0, ev1, 0);
  cudaStreamWaitEvent(0, ev2, 0);
  cudaStreamWaitEvent(0, ev3, 0);

  tg2_k<128,true,false><<<dim3(4,1024),256,SMEM128>>>(wh+W_FC1, wl+W_FC1, 256,
      BSCopy{ph,pl}, EpSplitStore{bh,bl}, psum, psq, 512, nullptr, nullptr);
  bn_fin_k<<<512,T>>>(psum,psq,512, mean+448, istd+448);
  tg2_k<128,false,true><<<dim3(2,1024),256,SMEM128>>>(wh+W_FC2, wl+W_FC2, 512,
      BSCopy{bh,bl}, EpResidual{out,x}, nullptr,nullptr,0, mean+448, istd+448);
}

// round 16
// speedup vs baseline: 1.1995x; 1.0220x over previous
#include <cuda_runtime.h>
#include <cuda_bf16.h>
#include <math.h>

#define EPSF 1e-5f
typedef __nv_bfloat16 bf16;

// ---------------- scratch -----------------------------------------------------
__device__ bf16  g_ph[33554432];
__device__ bf16  g_pl[33554432];
__device__ bf16  g_bh[67108864];
__device__ bf16  g_bl[67108864];
__device__ bf16  g_xh[16777216];
__device__ bf16  g_xl[16777216];
__device__ bf16  g_wh[524288];
__device__ bf16  g_wl[524288];
__device__ float g_psum[524288];
__device__ float g_psq[524288];
__device__ float g_tmp[8388608];
__device__ float g_xm[32*64*484];
__device__ float g_gsum[32*64*484];
__device__ float g_x4p[32*64*1024];
__device__ unsigned char g_idx1[32*64*1024];
__device__ float g_xp[32*64*256];
__device__ unsigned char g_idx2[32*64*256];
__device__ float g_hb[32*64*256];
__device__ float g_a1b[32*64*256];
__device__ float g_a2b[32*64*256];
__device__ float g_a1s[32*32*256];
__device__ float g_a2s[32*32*256];
__device__ float g_sigb[32*2*256];
__device__ float g_attnb[32*64*256];
__device__ float g_gaout[32*64*1024];
__device__ float g_mean[1024];
__device__ float g_istd[1024];

__device__ __forceinline__ float sigmoidf_(float v){ return 1.0f/(1.0f+expf(-v)); }
__device__ __forceinline__ void split_store(float v, bf16* h, bf16* l, size_t i){
  bf16 hh=__float2bfloat16(v);
  h[i]=hh; l[i]=__float2bfloat16(v-__bfloat162float(hh));
}
__device__ __forceinline__ void cpa16(void* s, const void* g){
  unsigned sa=(unsigned)__cvta_generic_to_shared(s);
  asm volatile("cp.async.ca.shared.global [%0],[%1],16;"::"r"(sa),"l"(g));
}
__device__ __forceinline__ void ldmx4(unsigned* r, const bf16* p){
  unsigned a=(unsigned)__cvta_generic_to_shared(p);
  asm volatile("ldmatrix.sync.aligned.m8n8.x4.shared.b16 {%0,%1,%2,%3},[%4];"
   :"=r"(r[0]),"=r"(r[1]),"=r"(r[2]),"=r"(r[3]):"r"(a));
}
__device__ __forceinline__ void ldmx4t(unsigned* r, const bf16* p){
  unsigned a=(unsigned)__cvta_generic_to_shared(p);
  asm volatile("ldmatrix.sync.aligned.m8n8.x4.trans.shared.b16 {%0,%1,%2,%3},[%4];"
   :"=r"(r[0]),"=r"(r[1]),"=r"(r[2]),"=r"(r[3]):"r"(a));
}
__device__ __forceinline__ void mma16816(float* c,const unsigned* a,const unsigned* b){
  asm volatile("mma.sync.aligned.m16n8k16.row.col.f32.bf16.bf16.f32 "
    "{%0,%1,%2,%3},{%4,%5,%6,%7},{%8,%9},{%0,%1,%2,%3};"
    :"+f"(c[0]),"+f"(c[1]),"+f"(c[2]),"+f"(c[3])
    :"r"(a[0]),"r"(a[1]),"r"(a[2]),"r"(a[3]),"r"(b[0]),"r"(b[1]));
}

// ---------------- B stagers (BK=16) --------------------------------------------
#define PBP 136
struct BSCopy {
  const bf16 *bh, *bl;
  __device__ __forceinline__ void stage(bf16* Bh, bf16* Bl, int k0, int n0, int tid) const {
    int k=tid>>4, nc=(tid&15)*8;
    cpa16(&Bh[k*PBP+nc], bh+(size_t)(k0+k)*131072+n0+nc);
    cpa16(&Bl[k*PBP+nc], bl+(size_t)(k0+k)*131072+n0+nc);
  }
};
struct BSXSplit {             // fp32 x channels (c0..): split-on-stage (plain STS)
  const float* x; int c0;
  __device__ __forceinline__ void stage(bf16* Bh, bf16* Bl, int k0, int n0, int tid) const {
    int k=tid>>4, nc=(tid&15)*8;
    int na=n0+nc; int b=na>>12, p=na&4095;
    const float* src=x+((size_t)(b*256+c0+k0+k)<<12)+p;
    float4 v0=*(const float4*)src, v1=*(const float4*)(src+4);
    float vv[8]={v0.x,v0.y,v0.z,v0.w,v1.x,v1.y,v1.z,v1.w};
#pragma unroll
    for(int e=0;e<8;e++){
      bf16 hh=__float2bfloat16(vv[e]);
      Bh[k*PBP+nc+e]=hh;
      Bl[k*PBP+nc+e]=__float2bfloat16(vv[e]-__bfloat162float(hh));
    }
  }
};
struct BSIm2col {
  const bf16 *xh, *xl;
  __device__ __forceinline__ void stage(bf16* Bh, bf16* Bl, int k0, int n0, int tid) const {
#pragma unroll
    for(int it=0;it<8;it++){
      int id=it*256+tid; int k=id>>7, n=id&127;
      int kk=k0+k;
      int ic=kk/9; int t=kk-ic*9; int dy=t/3-1, dx=t%3-1;
      int na=n0+n; int p=na&4095;
      int h=(p>>6)+dy, w=(p&63)+dx;
      bf16 vh, vl;
      if((unsigned)h>63u||(unsigned)w>63u){ vh=__float2bfloat16(0.f); vl=vh; }
      else{
        size_t gi=(size_t)ic*131072+(size_t)(na&~4095)+h*64+w;
        vh=xh[gi]; vl=xl[gi];
      }
      Bh[k*PBP+n]=vh; Bl[k*PBP+n]=vl;
    }
  }
};

// ---------------- epilogues ---------------------------------------------------
struct EpStore {
  float* o; int MC; int oc0;
  __device__ __forceinline__ void operator()(int m,int n,float a) const {
    int b=n>>12,p=n&4095;
    o[((size_t)(b*MC+oc0+m)<<12)+p]=a;
  }
};
struct EpSplitStore {
  bf16 *oh,*ol;
  __device__ __forceinline__ void operator()(int m,int n,float a) const {
    split_store(a, oh, ol, (size_t)m*131072+n);
  }
};
struct EpGateMulSplit {
  bf16 *ph,*pl; const float* x;
  __device__ __forceinline__ void operator()(int m,int n,float a) const {
    int b=n>>12,p=n&4095;
    float v=x[((size_t)(b*256+m)<<12)+p]*sigmoidf_(a);
    split_store(v, ph, pl, (size_t)m*131072+n);
  }
};
struct EpResidual {
  float* o; const float* x;
  __device__ __forceinline__ void operator()(int m,int n,float a) const {
    int b=n>>12,p=n&4095;
    size_t i=((size_t)(b*256+m)<<12)+p;
    o[i]=x[i]+a;
  }
};

// ------- GEMM: triple-buffered, ONE barrier per k-tile, BK=16, 3-pass MMA -------
#define PA_ 24
#define SMEM128 (6*128*PA_*2 + 6*16*PBP*2)
#define SMEM64  (6*64*PA_*2  + 6*16*PBP*2)
template<int BM,int MINB,bool STATS,bool BNORMOWN,class BS,class EP>
__global__ __launch_bounds__(256,MINB)
void tg2_k(const bf16* __restrict__ wh, const bf16* __restrict__ wl,
           int K, BS bs, EP ep,
           float* __restrict__ psum, float* __restrict__ psq, int C,
           const float* __restrict__ mean, const float* __restrict__ istd){
  constexpr int WTM=BM/2, MI=WTM/16;
  extern __shared__ __align__(16) bf16 SM[];
  bf16* Ah=SM;                 // [3][BM*PA_]
  bf16* Al=SM+3*BM*PA_;
  bf16* Bhs=SM+6*BM*PA_;       // [3][16*PBP]
  bf16* Bls=SM+6*BM*PA_+3*16*PBP;
  __shared__ float sS4[4*BM], sQ4[4*BM];
  const int tid=threadIdx.x;
  const int warp=tid>>5, lane=tid&31;
  const int wm=warp>>2, wn=warp&3;
  const int m0=blockIdx.x*BM, n0=blockIdx.y*128;
  float c[MI][4][4];
#pragma unroll
  for(int i=0;i<MI;i++)
#pragma unroll
    for(int j=0;j<4;j++)
#pragma unroll
      for(int q=0;q<4;q++) c[i][j][q]=0.f;
  auto stageA=[&](int buf,int k0){
    for(int id=tid; id<BM*2; id+=256){
      int m=id>>1, kc=(id&1)*8;
      cpa16(&Ah[buf*BM*PA_+m*PA_+kc], wh+(size_t)(m0+m)*K+k0+kc);
      cpa16(&Al[buf*BM*PA_+m*PA_+kc], wl+(size_t)(m0+m)*K+k0+kc);
    }
  };
  const int KT=K/16;
  stageA(0,0); bs.stage(Bhs,Bls,0,n0,tid);
  asm volatile("cp.async.commit_group;");
  if(KT>1){
    stageA(1,16); bs.stage(Bhs+16*PBP,Bls+16*PBP,16,n0,tid);
    asm volatile("cp.async.commit_group;");
  }
  for(int kt=0;kt<KT;kt++){
    const int buf=kt%3;
    bf16* bh_=Bhs+buf*16*PBP;
    bf16* bl_=Bls+buf*16*PBP;
    if(kt+1<KT) asm volatile("cp.async.wait_group 1;");
    else        asm volatile("cp.async.wait_group 0;");
    if(BNORMOWN){
      int k=tid>>4, nc=(tid&15)*8;
      float mm=__ldg(&mean[kt*16+k]), is=__ldg(&istd[kt*16+k]);
      bf16* bph=&bh_[k*PBP+nc];
      bf16* bpl=&bl_[k*PBP+nc];
#pragma unroll
      for(int e=0;e<8;e++){
        float v=__bfloat162float(bph[e])+__bfloat162float(bpl[e]);
        v=(v-mm)*is; v=v>0.f?v:0.f;
        bf16 hh=__float2bfloat16(v);
        bph[e]=hh; bpl[e]=__float2bfloat16(v-__bfloat162float(hh));
      }
    }
    __syncthreads();                 // single barrier per k-tile
    if(kt+2<KT){
      int nb=(kt+2)%3;
      stageA(nb,(kt+2)*16);
      bs.stage(Bhs+nb*16*PBP,Bls+nb*16*PBP,(kt+2)*16,n0,tid);
      asm volatile("cp.async.commit_group;");
    }
    // ---- compute buf: 3 passes of independent MMAs ----
    const int arow=lane&15, acol=(lane>>4)<<3;
    const bf16* ah_=Ah+buf*BM*PA_;
    const bf16* al_=Al+buf*BM*PA_;
    unsigned a4[MI][4];
    unsigned b4h[2][4], b4l[2][4];
#pragma unroll
    for(int np=0;np<2;np++){
      int rb=(lane&15)*PBP+wn*32+np*16+((lane>>4)<<3);
      ldmx4t(b4h[np], &bh_[rb]);
      ldmx4t(b4l[np], &bl_[rb]);
    }
#pragma unroll
    for(int mi=0;mi<MI;mi++)
      ldmx4(a4[mi], &ah_[(wm*WTM+mi*16+arow)*PA_+acol]);
#pragma unroll
    for(int np=0;np<2;np++)
#pragma unroll
      for(int t2=0;t2<2;t2++)
#pragma unroll
        for(int mi=0;mi<MI;mi++)
          mma16816(c[mi][np*2+t2], a4[mi], &b4h[np][t2*2]);
#pragma unroll
    for(int np=0;np<2;np++)
#pragma unroll
      for(int t2=0;t2<2;t2++)
#pragma unroll
        for(int mi=0;mi<MI;mi++)
          mma16816(c[mi][np*2+t2], a4[mi], &b4l[np][t2*2]);
#pragma unroll
    for(int mi=0;mi<MI;mi++)
      ldmx4(a4[mi], &al_[(wm*WTM+mi*16+arow)*PA_+acol]);
#pragma unroll
    for(int np=0;np<2;np++)
#pragma unroll
      for(int t2=0;t2<2;t2++)
#pragma unroll
        for(int mi=0;mi<MI;mi++)
          mma16816(c[mi][np*2+t2], a4[mi], &b4h[np][t2*2]);
  }
  __syncthreads();
  if(STATS){
#pragma unroll
    for(int mi=0;mi<MI;mi++){
      float s1=0.f,q1=0.f,s2=0.f,q2=0.f;
#pragma unroll
      for(int ni=0;ni<4;ni++){
        s1+=c[mi][ni][0]+c[mi][ni][1];
        q1+=c[mi][ni][0]*c[mi][ni][0]+c[mi][ni][1]*c[mi][ni][1];
        s2+=c[mi][ni][2]+c[mi][ni][3];
        q2+=c[mi][ni][2]*c[mi][ni][2]+c[mi][ni][3]*c[mi][ni][3];
      }
#pragma unroll
      for(int off=1;off<4;off<<=1){
        s1+=__shfl_xor_sync(0xffffffffu,s1,off);
        q1+=__shfl_xor_sync(0xffffffffu,q1,off);
        s2+=__shfl_xor_sync(0xffffffffu,s2,off);
        q2+=__shfl_xor_sync(0xffffffffu,q2,off);
      }
      if((lane&3)==0){
        int mr=wm*WTM+mi*16+(lane>>2);
        sS4[wn*BM+mr]=s1; sQ4[wn*BM+mr]=q1;
        sS4[wn*BM+mr+8]=s2; sQ4[wn*BM+mr+8]=q2;
      }
    }
    __syncthreads();
    for(int i=tid;i<BM;i+=256){
      float s=sS4[i]+sS4[BM+i]+sS4[2*BM+i]+sS4[3*BM+i];
      float q=sQ4[i]+sQ4[BM+i]+sQ4[2*BM+i]+sQ4[3*BM+i];
      psum[(size_t)blockIdx.y*C+m0+i]=s;
      psq [(size_t)blockIdx.y*C+m0+i]=q;
    }
  }
  const int r=lane>>2, q=lane&3;
#pragma unroll
  for(int mi=0;mi<MI;mi++)
#pragma unroll
    for(int ni=0;ni<4;ni++){
      int m=m0+wm*WTM+mi*16+r;
      int n=n0+wn*32+ni*8+2*q;
      ep(m,   n,   c[mi][ni][0]);
      ep(m,   n+1, c[mi][ni][1]);
      ep(m+8, n,   c[mi][ni][2]);
      ep(m+8, n+1, c[mi][ni][3]);
    }
}

// ---------------- stats finalize -----------------------------------------------
__global__ void bn_fin_k(const float* __restrict__ psum, const float* __restrict__ psq,
                         int C, float* __restrict__ mean, float* __restrict__ istd){
  int c=blockIdx.x;
  float s=0.f,q=0.f;
  for(int i=threadIdx.x;i<1024;i+=256){ s+=psum[(size_t)i*C+c]; q+=psq[(size_t)i*C+c]; }
  __shared__ float sh[256], sh2[256];
  sh[threadIdx.x]=s; sh2[threadIdx.x]=q; __syncthreads();
  for(int o=128;o>0;o>>=1){
    if(threadIdx.x<o){ sh[threadIdx.x]+=sh[threadIdx.x+o]; sh2[threadIdx.x]+=sh2[threadIdx.x+o]; }
    __syncthreads();
  }
  if(threadIdx.x==0){
    float m=sh[0]*(1.f/131072.f);
    float v=sh2[0]*(1.f/131072.f)-m*m;
    mean[c]=m; istd[c]=rsqrtf(v+EPSF);
  }
}

// ---------------- split kernels ---------------------------------------------------
__global__ void wsplit_all_k(const float* __restrict__ w1,const float* __restrict__ w2,
                             const float* __restrict__ w3,const float* __restrict__ w4,
                             const float* __restrict__ w5,
                             bf16* __restrict__ h, bf16* __restrict__ l){
  int i=blockIdx.x*blockDim.x+threadIdx.x;
  if(i>=331776) return;
  const float* src; int off;
  if(i<16384){src=w1;off=0;}
  else if(i<32768){src=w2;off=16384;}
  else if(i<69632){src=w3;off=32768;}
  else if(i<200704){src=w4;off=69632;}
  else {src=w5;off=200704;}
  split_store(src[i-off], h, l, i);
}
__global__ void xsplit_k(const float* __restrict__ x, bf16* __restrict__ xh,
                         bf16* __restrict__ xl){
  int i=blockIdx.x*blockDim.x+threadIdx.x;
  if(i>=32*64*4096) return;
  int p=i&4095; int bc=i>>12; int ch=bc&63; int b=bc>>6;
  float v=x[((size_t)(b*256+64+ch)<<12)+p];
  split_store(v, xh, xl, (size_t)ch*131072+b*4096+p);
}
__global__ void bn_stats_k(const float* __restrict__ d, int C, int S,
                           float* __restrict__ mean, float* __restrict__ istd){
  int c=blockIdx.x;
  double s=0.0,s2=0.0;
  for(int b=0;b<32;b++){
    const float* P=d+(size_t)(b*C+c)*S;
    for(int off=threadIdx.x;off<S;off+=256){
      float v=P[off]; s+=(double)v; s2+=(double)v*(double)v;
    }
  }
  __shared__ double sh[256], sh2[256];
  sh[threadIdx.x]=s; sh2[threadIdx.x]=s2; __syncthreads();
  for(int o=128;o>0;o>>=1){
    if(threadIdx.x<o){ sh[threadIdx.x]+=sh[threadIdx.x+o]; sh2[threadIdx.x]+=sh2[threadIdx.x+o]; }
    __syncthreads();
  }
  if(threadIdx.x==0){
    double N=32.0*(double)S;
    double m=sh[0]/N, v=sh2[0]/N-m*m;
    mean[c]=(float)m; istd[c]=rsqrtf((float)v+EPSF);
  }
}
__global__ void la_apply_k(const float* __restrict__ t, bf16* __restrict__ ph,
                           bf16* __restrict__ pl,
                           const float* __restrict__ mean, const float* __restrict__ istd){
  int i=blockIdx.x*blockDim.x+threadIdx.x;
  if(i>=32*64*4096) return;
  int p=i&4095; int bc=i>>12; int c=bc&63; int b=bc>>6;
  float v=(t[i]-mean[c])*istd[c];
  v=v>0.f?v:0.f;
  split_store(v, ph, pl, (size_t)(64+c)*131072+b*4096+p);
}
__global__ void blurpool_k(const float* __restrict__ x, float* __restrict__ xm){
  int i=blockIdx.x*blockDim.x+threadIdx.x;
  if(i>=32*64*484) return;
  int s=i%484; int bc=i/484; int c=bc&63; int b=bc>>6;
  const float* X=x+(((size_t)(b*256+128+c))<<12);
  int oh=s/22, ow=s%22;
  const float f0[4]={1.f,3.f,3.f,1.f};
  float acc=0.f;
  for(int iy=0;iy<4;iy++){
    int u=3*oh+iy-1; u=u<0?-u:u; u=u>63?126-u:u;
    float fy=f0[iy];
    for(int ix=0;ix<4;ix++){
      int v=3*ow+ix-1; v=v<0?-v:v; v=v>63?126-v:v;
      float m=-3.4e38f;
      for(int dy=-1;dy<=1;dy++){
        int yy=u+dy; if((unsigned)yy>63u) continue;
        for(int dx=-1;dx<=1;dx++){
          int xx=v+dx; if((unsigned)xx>63u) continue;
          float vv=X[yy*64+xx]; m=vv>m?vv:m;
        }
      }
      acc+=fy*f0[ix]*m;
    }
  }
  xm[i]=acc*(1.f/64.f);
}
__global__ void mra_strips_k(const float* __restrict__ wh1, const float* __restrict__ wv1,
                             const float* __restrict__ wh2, const float* __restrict__ wv2,
                             const float* __restrict__ xm, float* __restrict__ gsum){
  int i=blockIdx.x*blockDim.x+threadIdx.x;
  if(i>=32*64*484) return;
  int s=i%484; int bc=i/484; int c=bc&63;
  int r=s/22, cc=s%22;
  const float* X=xm+(size_t)bc*484;
  const float* W1=wh1+c*33; const float* V1=wv1+c*33;
  const float* W2=wh2+c*33; const float* V2=wv2+c*33;
  float acc=0.f;
  for(int ky=0;ky<11;ky++){
    int y=r+ky-5; if((unsigned)y>=22u) continue;
    for(int kx=0;kx<3;kx++){
      int x2=cc+kx-1; if((unsigned)x2>=22u) continue;
      acc+=W1[ky*3+kx]*X[y*22+x2];
    }
  }
  for(int ky=0;ky<3;ky++){
    int y=r+ky-1; if((unsigned)y>=22u) continue;
    for(int kx=0;kx<11;kx++){
      int x2=cc+kx-5; if((unsigned)x2>=22u) continue;
      acc+=V1[ky*11+kx]*X[y*22+x2];
    }
  }
  {
    int i2=r*44+cc; int R=i2/43, C=i2-43*R;
    for(int ky=0;ky<11;ky++){
      int RR=R+ky-5; if((unsigned)RR>=22u) continue;
      for(int kx=0;kx<3;kx++){
        int CC=C+kx-1; if((unsigned)CC>=43u) continue;
        int j=RR*43+CC; int q=j/44, m=j-44*q;
        if(m<22) acc+=W2[ky*3+kx]*X[q*22+m];
      }
    }
  }
  {
    int j=cc*44+r; int b2=j/43, a2=j-43*b2;
    for(int ky=0;ky<3;ky++){
      int RR=a2+ky-1; if((unsigned)RR>=43u) continue;
      for(int kx=0;kx<11;kx++){
        int CC=b2+kx-5; if((unsigned)CC>=22u) continue;
        int j2=CC*43+RR; int q=j2/44, m=j2-44*q;
        if(m<22) acc+=V2[ky*11+kx]*X[m*22+q];
      }
    }
  }
  gsum[i]=acc;
}
__global__ void mra_apply_k(const float* __restrict__ x, const float* __restrict__ gsum,
                            bf16* __restrict__ ph, bf16* __restrict__ pl,
                            const float* __restrict__ mean, const float* __restrict__ istd){
  int i=blockIdx.x*blockDim.x+threadIdx.x;
  if(i>=32*64*4096) return;
  int p=i&4095, bc=i>>12, c=bc&63, b=bc>>6;
  int h=p>>6, w=p&63;
  int ri=(h*22)>>6, ci=(w*22)>>6;
  float g=gsum[(size_t)bc*484+ri*22+ci];
  g=sigmoidf_((g-mean[c])*istd[c]);
  float v=x[((size_t)(b*256+128+c)<<12)+p]*g;
  split_store(v, ph, pl, (size_t)(128+c)*131072+b*4096+p);
}
__global__ void pool2_k(const float* __restrict__ in, long bstride, int c0, int inW,
                        float* __restrict__ out, unsigned char* __restrict__ idx, int total){
  int i=blockIdx.x*blockDim.x+threadIdx.x;
  if(i>=total) return;
  int outW=inW>>1; int os=outW*outW;
  int s=i%os; int bc=i/os; int b=bc>>6, c=bc&63;
  int oh=s/outW, ow=s-oh*outW;
  const float* P=in+(size_t)b*bstride+(size_t)(c0+c)*inW*inW;
  float v0=P[(2*oh)*inW+2*ow],   v1=P[(2*oh)*inW+2*ow+1];
  float v2=P[(2*oh+1)*inW+2*ow], v3=P[(2*oh+1)*inW+2*ow+1];
  float best=v0; int bi=0;
  if(v1>best){best=v1;bi=1;}
  if(v2>best){best=v2;bi=2;}
  if(v3>best){best=v3;bi=3;}
  out[i]=best; idx[i]=(unsigned char)bi;
}
__global__ void ga_proj1_k(const float* __restrict__ xp, const float* __restrict__ w,
                           const float* __restrict__ bias, float* __restrict__ hb){
  int i=blockIdx.x*blockDim.x+threadIdx.x;
  if(i>=32*64*256) return;
  int s=i&255; int boc=i>>8; int oc=boc&63; int b=boc>>6;
  const float* X=xp+(size_t)b*64*256;
  float acc=bias[oc];
  for(int ic=0;ic<64;ic++) acc+=w[oc*64+ic]*X[ic*256+s];
  hb[i]=acc>0.f?acc:0.f;
}
__global__ void ga_dw_k(const float* __restrict__ hb,
                        const float* __restrict__ c0w, const float* __restrict__ c0b,
                        const float* __restrict__ spw, const float* __restrict__ spb,
                        float* __restrict__ a1, float* __restrict__ a2){
  int bc=blockIdx.x; int c=bc&63;
  int s=threadIdx.x;
  int y=s>>4, x=s&15;
  __shared__ float A1[256];
  const float* H=hb+(size_t)bc*256;
  float acc=c0b[c];
  for(int ky=0;ky<5;ky++){
    int yy=y+ky-2; if((unsigned)yy>15u) continue;
    for(int kx=0;kx<5;kx++){
      int xx=x+kx-2; if((unsigned)xx>15u) continue;
      acc+=c0w[c*25+ky*5+kx]*H[yy*16+xx];
    }
  }
  A1[s]=acc; a1[(size_t)bc*256+s]=acc;
  __syncthreads();
  float acc2=spb[c];
  for(int ky=0;ky<7;ky++){
    int yy=y+3*ky-9; if((unsigned)yy>15u) continue;
    for(int kx=0;kx<7;kx++){
      int xx=x+3*kx-9; if((unsigned)xx>15u) continue;
      acc2+=spw[c*49+ky*7+kx]*A1[yy*16+xx];
    }
  }
  a2[(size_t)bc*256+s]=acc2;
}
__global__ void ga_c1c2_k(const float* __restrict__ a1, const float* __restrict__ a2,
                          const float* __restrict__ c1w, const float* __restrict__ c1b,
                          const float* __restrict__ c2w, const float* __restrict__ c2b,
                          float* __restrict__ a1s, float* __restrict__ a2s){
  int i=blockIdx.x*blockDim.x+threadIdx.x;
  if(i>=2*32*32*256) return;
  int which=i/(32*32*256); int rr=i-which*(32*32*256);
  int s=rr&255; int bj=rr>>8; int j=bj&31; int b=bj>>5;
  const float* src=which?a2:a1;
  const float* W=which?c2w:c1w;
  const float* Bb=which?c2b:c1b;
  const float* S=src+(size_t)b*64*256;
  float acc=Bb[j];
  for(int ic=0;ic<64;ic++) acc+=W[j*64+ic]*S[ic*256+s];
  (which?a2s:a1s)[(size_t)(b*32+j)*256+s]=acc;
}
__global__ void ga_aggsq_k(const float* __restrict__ a1s, const float* __restrict__ a2s,
                           const float* __restrict__ sqw, const float* __restrict__ sqb,
                           float* __restrict__ sg){
  int b=blockIdx.x; int s=threadIdx.x;
  __shared__ float AG[2][256];
  const float* A1=a1s+(size_t)b*32*256;
  const float* A2=a2s+(size_t)b*32*256;
  float sum=0.f, mx=-3.4e38f;
  for(int j=0;j<32;j++){
    float v1=A1[j*256+s]; sum+=v1; mx=v1>mx?v1:mx;
    float v2=A2[j*256+s]; sum+=v2; mx=v2>mx?v2:mx;
  }
  AG[0][s]=sum*(1.f/64.f); AG[1][s]=mx;
  __syncthreads();
  int y=s>>4, x=s&15;
  for(int o=0;o<2;o++){
    float acc=sqb[o];
    for(int ic=0;ic<2;ic++){
      const float* W=sqw+((o*2+ic)*49);
      for(int ky=0;ky<7;ky++){
        int yy=y+ky-3; if((unsigned)yy>15u) continue;
        for(int kx=0;kx<7;kx++){
          int xx=x+kx-3; if((unsigned)xx>15u) continue;
          acc+=W[ky*7+kx]*AG[ic][yy*16+xx];
        }
      }
    }
    sg[(size_t)(b*2+o)*256+s]=sigmoidf_(acc);
  }
}
__global__ void ga_attn_k(const float* __restrict__ a1s, const float* __restrict__ a2s,
                          const float* __restrict__ sg, const float* __restrict__ cw,
                          const float* __restrict__ cb, float* __restrict__ attn){
  int i=blockIdx.x*blockDim.x+threadIdx.x;
  if(i>=32*64*256) return;
  int s=i&255; int boc=i>>8; int oc=boc&63; int b=boc>>6;
  float s0=sg[(size_t)(b*2+0)*256+s];
  float s1=sg[(size_t)(b*2+1)*256+s];
  const float* A1=a1s+(size_t)b*32*256;
  const float* A2=a2s+(size_t)b*32*256;
  float acc=cb[oc];
  for(int j=0;j<32;j++)
    acc+=cw[oc*32+j]*(A1[j*256+s]*s0+A2[j*256+s]*s1);
  attn[i]=acc;
}
__global__ void ga_proj2_unpool_k(const float* __restrict__ hb, const float* __restrict__ attn,
                                  const float* __restrict__ w, const float* __restrict__ bias,
                                  const unsigned char* __restrict__ idx2, float* __restrict__ out){
  int i=blockIdx.x*blockDim.x+threadIdx.x;
  if(i>=32*64*256) return;
  int s=i&255; int boc=i>>8; int oc=boc&63; int b=boc>>6;
  const float* H=hb+(size_t)b*64*256;
  const float* A=attn+(size_t)b*64*256;
  float acc=bias[oc];
  for(int ic=0;ic<64;ic++) acc+=w[oc*64+ic]*H[ic*256+s]*A[ic*256+s];
  int id=idx2[i];
  int y=s>>4, x=s&15;
  float* O=out+(size_t)boc*1024;
  for(int dy=0;dy<2;dy++)
    for(int dx=0;dx<2;dx++)
      O[(2*y+dy)*32+2*x+dx]=(dy*2+dx==id)?acc:0.f;
}
__global__ void ga_final_k(const float* __restrict__ gaout, const unsigned char* __restrict__ idx1,
                           bf16* __restrict__ ph, bf16* __restrict__ pl,
                           const float* __restrict__ mean, const float* __restrict__ istd){
  int i=blockIdx.x*blockDim.x+threadIdx.x;
  if(i>=32*64*1024) return;
  int s=i&1023; int bc=i>>10; int c=bc&63; int b=bc>>6;
  float v=(gaout[i]-mean[c])*istd[c];
  int id=idx1[i];
  int y=s>>5, x=s&31;
  size_t base=(size_t)(192+c)*131072+b*4096;
  for(int dy=0;dy<2;dy++)
    for(int dx=0;dx<2;dx++){
      float o=(dy*2+dx==id)?v:0.f;
      split_store(o, ph, pl, base+(2*y+dy)*64+2*x+dx);
    }
}

// ---------------- launch ----------------------------------------------------------
extern "C" void kernel_launch(void* const* d_in, const int* in_sizes, int n_in,
                              void* d_out, int out_size) {
  const float* x      =(const float*)d_in[0];
  const float* pa_w1  =(const float*)d_in[1];
  const float* pa_w2  =(const float*)d_in[2];
  const float* la_w   =(const float*)d_in[3];
  const float* mra_h1 =(const float*)d_in[4];
  const float* mra_v1 =(const float*)d_in[5];
  const float* mra_h2 =(const float*)d_in[6];
  const float* mra_v2 =(const float*)d_in[7];
  const float* p1w=(const float*)d_in[8];  const float* p1b=(const float*)d_in[9];
  const float* c0w=(const float*)d_in[10]; const float* c0b=(const float*)d_in[11];
  const float* spw=(const float*)d_in[12]; const float* spb=(const float*)d_in[13];
  const float* c1w=(const float*)d_in[14]; const float* c1b=(const float*)d_in[15];
  const float* c2w=(const float*)d_in[16]; const float* c2b=(const float*)d_in[17];
  const float* cw =(const float*)d_in[18]; const float* cb =(const float*)d_in[19];
  const float* sqw=(const float*)d_in[20]; const float* sqb=(const float*)d_in[21];
  const float* p2w=(const float*)d_in[22]; const float* p2b=(const float*)d_in[23];
  const float* mlp_w1=(const float*)d_in[24];
  const float* mlp_w2=(const float*)d_in[25];
  float* out=(float*)d_out;

  float *tmp,*xm,*gsum,*x4p,*xp,*hb,*a1b,*a2b,*a1s,*a2s,*sigb,*attnb,*gaout,*mean,*istd,*psum,*psq;
  bf16 *ph,*pl,*bh,*bl,*xh,*xl,*wh,*wl;
  unsigned char *idx1,*idx2;
  cudaGetSymbolAddress((void**)&ph,g_ph);   cudaGetSymbolAddress((void**)&pl,g_pl);
  cudaGetSymbolAddress((void**)&bh,g_bh);   cudaGetSymbolAddress((void**)&bl,g_bl);
  cudaGetSymbolAddress((void**)&xh,g_xh);   cudaGetSymbolAddress((void**)&xl,g_xl);
  cudaGetSymbolAddress((void**)&wh,g_wh);   cudaGetSymbolAddress((void**)&wl,g_wl);
  cudaGetSymbolAddress((void**)&psum,g_psum); cudaGetSymbolAddress((void**)&psq,g_psq);
  cudaGetSymbolAddress((void**)&tmp,g_tmp); cudaGetSymbolAddress((void**)&xm,g_xm);
  cudaGetSymbolAddress((void**)&gsum,g_gsum); cudaGetSymbolAddress((void**)&x4p,g_x4p);
  cudaGetSymbolAddress((void**)&xp,g_xp);   cudaGetSymbolAddress((void**)&hb,g_hb);
  cudaGetSymbolAddress((void**)&a1b,g_a1b); cudaGetSymbolAddress((void**)&a2b,g_a2b);
  cudaGetSymbolAddress((void**)&a1s,g_a1s); cudaGetSymbolAddress((void**)&a2s,g_a2s);
  cudaGetSymbolAddress((void**)&sigb,g_sigb); cudaGetSymbolAddress((void**)&attnb,g_attnb);
  cudaGetSymbolAddress((void**)&gaout,g_gaout);
  cudaGetSymbolAddress((void**)&mean,g_mean); cudaGetSymbolAddress((void**)&istd,g_istd);
  cudaGetSymbolAddress((void**)&idx1,g_idx1); cudaGetSymbolAddress((void**)&idx2,g_idx2);

  const int T=256;
  const int W_PA1=0, W_PA2=16384, W_LA=32768, W_FC1=69632, W_FC2=200704;

  static cudaStream_t s1=0,s2=0,s3=0;
  static cudaEvent_t evRoot=0,evW=0,ev1=0,ev2=0,ev3=0;
  if(!s1){
    cudaStreamCreateWithFlags(&s1,cudaStreamNonBlocking);
    cudaStreamCreateWithFlags(&s2,cudaStreamNonBlocking);
    cudaStreamCreateWithFlags(&s3,cudaStreamNonBlocking);
    cudaEventCreateWithFlags(&evRoot,cudaEventDisableTiming);
    cudaEventCreateWithFlags(&evW,cudaEventDisableTiming);
    cudaEventCreateWithFlags(&ev1,cudaEventDisableTiming);
    cudaEventCreateWithFlags(&ev2,cudaEventDisableTiming);
    cudaEventCreateWithFlags(&ev3,cudaEventDisableTiming);
    cudaFuncSetAttribute((const void*)tg2_k<128,2,true,false,BSXSplit,EpSplitStore>,
                         cudaFuncAttributeMaxDynamicSharedMemorySize, SMEM128);
    cudaFuncSetAttribute((const void*)tg2_k<64,3,false,true,BSCopy,EpGateMulSplit>,
                         cudaFuncAttributeMaxDynamicSharedMemorySize, SMEM64);
    cudaFuncSetAttribute((const void*)tg2_k<64,3,true,false,BSIm2col,EpStore>,
                         cudaFuncAttributeMaxDynamicSharedMemorySize, SMEM64);
    cudaFuncSetAttribute((const void*)tg2_k<128,2,true,false,BSCopy,EpSplitStore>,
                         cudaFuncAttributeMaxDynamicSharedMemorySize, SMEM128);
    cudaFuncSetAttribute((const void*)tg2_k<128,2,false,true,BSCopy,EpResidual>,
                         cudaFuncAttributeMaxDynamicSharedMemorySize, SMEM128);
  }

  cudaEventRecord(evRoot, 0);
  cudaStreamWaitEvent(s1, evRoot, 0);
  cudaStreamWaitEvent(s2, evRoot, 0);
  cudaStreamWaitEvent(s3, evRoot, 0);

  // ---- s1: xsplit FIRST (needs only x), overlaps wsplit + PA1 ----
  xsplit_k<<<32768,T,0,s1>>>(x, xh, xl);

  // ---- main: weight split, then PA chain (PA1 reads fp32 x directly) ----
  wsplit_all_k<<<1296,T>>>(pa_w1,pa_w2,la_w,mlp_w1,mlp_w2, wh, wl);
  cudaEventRecord(evW, 0);

  tg2_k<128,2,true,false><<<dim3(2,1024),256,SMEM128>>>(wh+W_PA1, wl+W_PA1, 64,
      BSXSplit{x,0}, EpSplitStore{bh,bl}, psum, psq, 256, nullptr, nullptr);
  bn_fin_k<<<256,T>>>(psum,psq,256, mean+0, istd+0);
  tg2_k<64,3,false,true><<<dim3(1,1024),256,SMEM64>>>(wh+W_PA2, wl+W_PA2, 256,
      BSCopy{bh,bl}, EpGateMulSplit{ph,pl,x}, nullptr,nullptr,0, mean+0, istd+0);

  // ---- s1: LA chain (wait for weights) ----
  cudaStreamWaitEvent(s1, evW, 0);
  tg2_k<64,3,true,false><<<dim3(1,1024),256,SMEM64,s1>>>(wh+W_LA, wl+W_LA, 576,
      BSIm2col{xh, xl}, EpStore{tmp,64,0},
      psum+262144, psq+262144, 64, nullptr, nullptr);
  bn_fin_k<<<64,T,0,s1>>>(psum+262144,psq+262144,64, mean+256, istd+256);
  la_apply_k<<<32768,T,0,s1>>>(tmp, ph, pl, mean+256, istd+256);

  blurpool_k<<<3872,T,0,s2>>>(x, xm);
  mra_strips_k<<<3872,T,0,s2>>>(mra_h1, mra_v1, mra_h2, mra_v2, xm, gsum);
  bn_stats_k<<<64,T,0,s2>>>(gsum,64,484, mean+320, istd+320);
  mra_apply_k<<<32768,T,0,s2>>>(x, gsum, ph, pl, mean+320, istd+320);

  pool2_k<<<8192,T,0,s3>>>(x, 256L*4096L, 192, 64, x4p, idx1, 32*64*1024);
  pool2_k<<<2048,T,0,s3>>>(x4p, 64L*1024L, 0, 32, xp, idx2, 32*64*256);
  ga_proj1_k<<<2048,T,0,s3>>>(xp, p1w, p1b, hb);
  ga_dw_k<<<2048,T,0,s3>>>(hb, c0w, c0b, spw, spb, a1b, a2b);
  ga_c1c2_k<<<2048,T,0,s3>>>(a1b, a2b, c1w, c1b, c2w, c2b, a1s, a2s);
  ga_aggsq_k<<<32,T,0,s3>>>(a1s, a2s, sqw, sqb, sigb);
  ga_attn_k<<<2048,T,0,s3>>>(a1s, a2s, sigb, cw, cb, attnb);
  ga_proj2_unpool_k<<<2048,T,0,s3>>>(hb, attnb, p2w, p2b, idx2, gaout);
  bn_stats_k<<<64,T,0,s3>>>(gaout,64,1024, mean+384, istd+384);
  ga_final_k<<<8192,T,0,s3>>>(gaout, idx1, ph, pl, mean+384, istd+384);

  cudaEventRecord(ev1,s1); cudaEventRecord(ev2,s2); cudaEventRecord(ev3,s3);
  cudaStreamWaitEvent(0, ev1, 0);
  cudaStreamWaitEvent(0, ev2, 0);
  cudaStreamWaitEvent(0, ev3, 0);

  tg2_k<128,2,true,false><<<dim3(4,1024),256,SMEM128>>>(wh+W_FC1, wl+W_FC1, 256,
      BSCopy{ph,pl}, EpSplitStore{bh,bl}, psum, psq, 512, nullptr, nullptr);
  bn_fin_k<<<512,T>>>(psum,psq,512, mean+448, istd+448);
  tg2_k<128,2,false,true><<<dim3(2,1024),256,SMEM128>>>(wh+W_FC2, wl+W_FC2, 512,
      BSCopy{bh,bl}, EpResidual{out,x}, nullptr,nullptr,0, mean+448, istd+448);
}